// round 3
// baseline (speedup 1.0000x reference)
#include <cuda_runtime.h>
#include <math.h>

// Problem constants
#define BB 2
#define NN 2048
#define DM 256     // d_model = H*DH
#define HH 8
#define DHD 32

// Scratch (device globals: no allocations allowed)
__device__ float g_Q[BB * NN * DM];
__device__ float g_K[BB * NN * DM];
__device__ float g_V[BB * NN * DM];
__device__ float g_A[BB * NN * DM];   // attention output before Wo

// ---------------------------------------------------------------------------
// GEMM: C[M x 256] = A[M x 256] @ W[256 x 256]^T (+ optional bias)
// Block tile 64x64, BK=32, 256 threads, 4x4 microtile.
// ---------------------------------------------------------------------------
__global__ __launch_bounds__(256) void gemm_xwT(
    const float* __restrict__ A, const float* __restrict__ W,
    const float* __restrict__ bias, float* __restrict__ C)
{
    __shared__ float As[64][33];
    __shared__ float Ws[64][33];
    const int t  = threadIdx.x;
    const int tx = t & 15, ty = t >> 4;
    const int m0 = blockIdx.x * 64, n0 = blockIdx.y * 64;

    float acc[4][4] = {};

    for (int k0 = 0; k0 < 256; k0 += 32) {
        #pragma unroll
        for (int it = 0; it < 2; ++it) {
            int idx = t + it * 256;
            int row = idx >> 3;
            int c4  = (idx & 7) * 4;
            float4 av = *(const float4*)(A + (size_t)(m0 + row) * 256 + k0 + c4);
            As[row][c4 + 0] = av.x; As[row][c4 + 1] = av.y;
            As[row][c4 + 2] = av.z; As[row][c4 + 3] = av.w;
            float4 wv = *(const float4*)(W + (size_t)(n0 + row) * 256 + k0 + c4);
            Ws[row][c4 + 0] = wv.x; Ws[row][c4 + 1] = wv.y;
            Ws[row][c4 + 2] = wv.z; Ws[row][c4 + 3] = wv.w;
        }
        __syncthreads();

        #pragma unroll 8
        for (int kk = 0; kk < 32; ++kk) {
            float a[4], w[4];
            #pragma unroll
            for (int i = 0; i < 4; ++i) a[i] = As[ty + 16 * i][kk];
            #pragma unroll
            for (int j = 0; j < 4; ++j) w[j] = Ws[tx + 16 * j][kk];
            #pragma unroll
            for (int i = 0; i < 4; ++i)
                #pragma unroll
                for (int j = 0; j < 4; ++j)
                    acc[i][j] += a[i] * w[j];
        }
        __syncthreads();
    }

    #pragma unroll
    for (int i = 0; i < 4; ++i) {
        int m = m0 + ty + 16 * i;
        #pragma unroll
        for (int j = 0; j < 4; ++j) {
            int n = n0 + tx + 16 * j;
            float c = acc[i][j];
            if (bias) c += bias[n];
            C[(size_t)m * 256 + n] = c;
        }
    }
}

// ---------------------------------------------------------------------------
// Fused masked flash-attention, fp32.
// Grid: (N/128, H, B). Block: 256 threads (16x16).
// Each block: 128 query rows of one (b, h). Online softmax over m-tiles of 128.
// Thread (ty,tx): rows r = ty*8 + i (i<8); score cols m = tx + 16*j (j<8);
// output cols d = {tx, tx+16}.
// ---------------------------------------------------------------------------
__global__ __launch_bounds__(256) void attn_kernel(const float* __restrict__ adj)
{
    extern __shared__ float sm[];
    float* Qs = sm;                  // 128*33
    float* Ks = Qs + 128 * 33;       // 128*33
    float* Vs = Ks + 128 * 33;       // 128*33
    float* Ps = Vs + 128 * 33;       // 128*132 (adj tile, then P tile)

    const int t  = threadIdx.x;
    const int tx = t & 15, ty = t >> 4;
    const int r0 = blockIdx.x * 128;
    const int h  = blockIdx.y;
    const int b  = blockIdx.z;

    const float* Qg = g_Q + (size_t)b * NN * DM + h * DHD;
    const float* Kg = g_K + (size_t)b * NN * DM + h * DHD;
    const float* Vg = g_V + (size_t)b * NN * DM + h * DHD;
    const float* adjb = adj + (size_t)b * NN * NN;
    const float qscale = 0.17677669529663687f;  // 1/sqrt(32)

    // Load Q tile (pre-scaled)
    #pragma unroll
    for (int it = 0; it < 4; ++it) {
        int idx = t + it * 256;
        int row = idx >> 3;
        int c4  = (idx & 7) * 4;
        float4 v = *(const float4*)(Qg + (size_t)(r0 + row) * DM + c4);
        Qs[row * 33 + c4 + 0] = v.x * qscale;
        Qs[row * 33 + c4 + 1] = v.y * qscale;
        Qs[row * 33 + c4 + 2] = v.z * qscale;
        Qs[row * 33 + c4 + 3] = v.w * qscale;
    }

    float mstate[8], lstate[8], acc[8][2];
    #pragma unroll
    for (int i = 0; i < 8; ++i) {
        mstate[i] = -1e30f; lstate[i] = 0.0f;
        acc[i][0] = 0.0f;   acc[i][1] = 0.0f;
    }

    for (int m0 = 0; m0 < NN; m0 += 128) {
        __syncthreads();   // previous PV done; safe to overwrite tiles

        // K/V tiles
        #pragma unroll
        for (int it = 0; it < 4; ++it) {
            int idx = t + it * 256;
            int row = idx >> 3;
            int c4  = (idx & 7) * 4;
            float4 kv = *(const float4*)(Kg + (size_t)(m0 + row) * DM + c4);
            Ks[row * 33 + c4 + 0] = kv.x; Ks[row * 33 + c4 + 1] = kv.y;
            Ks[row * 33 + c4 + 2] = kv.z; Ks[row * 33 + c4 + 3] = kv.w;
            float4 vv = *(const float4*)(Vg + (size_t)(m0 + row) * DM + c4);
            Vs[row * 33 + c4 + 0] = vv.x; Vs[row * 33 + c4 + 1] = vv.y;
            Vs[row * 33 + c4 + 2] = vv.z; Vs[row * 33 + c4 + 3] = vv.w;
        }
        // adj tile -> Ps
        #pragma unroll
        for (int it = 0; it < 16; ++it) {
            int idx = t + it * 256;
            int row = idx >> 5;
            int c4  = (idx & 31) * 4;
            *(float4*)(Ps + row * 132 + c4) =
                *(const float4*)(adjb + (size_t)(r0 + row) * NN + m0 + c4);
        }
        __syncthreads();

        // S = Q @ K^T (register 8x8 microtile)
        float s[8][8];
        #pragma unroll
        for (int i = 0; i < 8; ++i)
            #pragma unroll
            for (int j = 0; j < 8; ++j) s[i][j] = 0.0f;

        #pragma unroll 8
        for (int d = 0; d < 32; ++d) {
            float q[8], k[8];
            #pragma unroll
            for (int i = 0; i < 8; ++i) q[i] = Qs[(ty * 8 + i) * 33 + d];
            #pragma unroll
            for (int j = 0; j < 8; ++j) k[j] = Ks[(tx + 16 * j) * 33 + d];
            #pragma unroll
            for (int i = 0; i < 8; ++i)
                #pragma unroll
                for (int j = 0; j < 8; ++j)
                    s[i][j] += q[i] * k[j];
        }

        // mask + online softmax + write P (each thread owns its (r,m) cells in Ps)
        #pragma unroll
        for (int i = 0; i < 8; ++i) {
            int r = ty * 8 + i;
            #pragma unroll
            for (int j = 0; j < 8; ++j) {
                float a = Ps[r * 132 + tx + 16 * j];
                if (a == 0.0f) s[i][j] = -1e30f;
            }
            float rmax = s[i][0];
            #pragma unroll
            for (int j = 1; j < 8; ++j) rmax = fmaxf(rmax, s[i][j]);
            #pragma unroll
            for (int o = 8; o >= 1; o >>= 1)
                rmax = fmaxf(rmax, __shfl_xor_sync(0xffffffffu, rmax, o, 16));

            float newm  = fmaxf(mstate[i], rmax);
            float scale = __expf(mstate[i] - newm);
            float psum  = 0.0f;
            #pragma unroll
            for (int j = 0; j < 8; ++j) {
                float p = (s[i][j] > -1e29f) ? __expf(s[i][j] - newm) : 0.0f;
                Ps[r * 132 + tx + 16 * j] = p;
                psum += p;
            }
            #pragma unroll
            for (int o = 8; o >= 1; o >>= 1)
                psum += __shfl_xor_sync(0xffffffffu, psum, o, 16);

            lstate[i] = lstate[i] * scale + psum;
            mstate[i] = newm;
            acc[i][0] *= scale;
            acc[i][1] *= scale;
        }
        __syncthreads();

        // acc += P @ V
        #pragma unroll 4
        for (int m = 0; m < 128; m += 4) {
            float4 p[8];
            #pragma unroll
            for (int i = 0; i < 8; ++i)
                p[i] = *(const float4*)(Ps + (ty * 8 + i) * 132 + m);
            float v0a = Vs[(m + 0) * 33 + tx], v0b = Vs[(m + 0) * 33 + tx + 16];
            float v1a = Vs[(m + 1) * 33 + tx], v1b = Vs[(m + 1) * 33 + tx + 16];
            float v2a = Vs[(m + 2) * 33 + tx], v2b = Vs[(m + 2) * 33 + tx + 16];
            float v3a = Vs[(m + 3) * 33 + tx], v3b = Vs[(m + 3) * 33 + tx + 16];
            #pragma unroll
            for (int i = 0; i < 8; ++i) {
                acc[i][0] += p[i].x * v0a + p[i].y * v1a + p[i].z * v2a + p[i].w * v3a;
                acc[i][1] += p[i].x * v0b + p[i].y * v1b + p[i].z * v2b + p[i].w * v3b;
            }
        }
    }

    // normalize + write
    #pragma unroll
    for (int i = 0; i < 8; ++i) {
        float inv = 1.0f / lstate[i];
        int r = r0 + ty * 8 + i;
        float* o = g_A + ((size_t)b * NN + r) * DM + h * DHD;
        o[tx]      = acc[i][0] * inv;
        o[tx + 16] = acc[i][1] * inv;
    }
}

// ---------------------------------------------------------------------------
// Launch
// ---------------------------------------------------------------------------
extern "C" void kernel_launch(void* const* d_in, const int* in_sizes, int n_in,
                              void* d_out, int out_size)
{
    const float* x   = (const float*)d_in[0];
    const float* adj = (const float*)d_in[1];
    const float* Wq  = (const float*)d_in[2];
    const float* Wk  = (const float*)d_in[3];
    const float* Wv  = (const float*)d_in[4];
    const float* Wo  = (const float*)d_in[5];
    const float* bo  = (const float*)d_in[6];
    float* out = (float*)d_out;

    float *Qp, *Kp, *Vp, *Ap;
    cudaGetSymbolAddress((void**)&Qp, g_Q);
    cudaGetSymbolAddress((void**)&Kp, g_K);
    cudaGetSymbolAddress((void**)&Vp, g_V);
    cudaGetSymbolAddress((void**)&Ap, g_A);

    const int attn_smem = (3 * 128 * 33 + 128 * 132) * (int)sizeof(float);  // 118272
    cudaFuncSetAttribute(attn_kernel,
                         cudaFuncAttributeMaxDynamicSharedMemorySize, attn_smem);

    dim3 ggemm(64, 4);   // M=4096 / 64, N=256 / 64
    gemm_xwT<<<ggemm, 256>>>(x, Wq, nullptr, Qp);
    gemm_xwT<<<ggemm, 256>>>(x, Wk, nullptr, Kp);
    gemm_xwT<<<ggemm, 256>>>(x, Wv, nullptr, Vp);

    attn_kernel<<<dim3(NN / 128, HH, BB), 256, attn_smem>>>(adj);

    gemm_xwT<<<ggemm, 256>>>(Ap, Wo, bo, out);
}

// round 6
// speedup vs baseline: 2.1162x; 2.1162x over previous
#include <cuda_runtime.h>
#include <cuda_bf16.h>
#include <math.h>

// Problem constants
#define BB 2
#define NN 2048
#define DM 256     // d_model = H*DH
#define HH 8
#define DHD 32
#define KS 40      // smem row stride (bf16 elems) for K/V tiles: 80B -> conflict-free ldmatrix

// Scratch (device globals: no allocations allowed)
__device__ float g_Q[BB * NN * DM];
__device__ float g_K[BB * NN * DM];
__device__ float g_V[BB * NN * DM];
__device__ float g_A[BB * NN * DM];   // attention output before Wo

// ---------------------------------------------------------------------------
// fp32 GEMM: C[M x 256] = A[M x 256] @ W[256 x 256]^T (+ optional bias)
// ---------------------------------------------------------------------------
__global__ __launch_bounds__(256) void gemm_xwT(
    const float* __restrict__ A, const float* __restrict__ W,
    const float* __restrict__ bias, float* __restrict__ C)
{
    __shared__ float As[64][33];
    __shared__ float Ws[64][33];
    const int t  = threadIdx.x;
    const int tx = t & 15, ty = t >> 4;
    const int m0 = blockIdx.x * 64, n0 = blockIdx.y * 64;

    float acc[4][4] = {};

    for (int k0 = 0; k0 < 256; k0 += 32) {
        #pragma unroll
        for (int it = 0; it < 2; ++it) {
            int idx = t + it * 256;
            int row = idx >> 3;
            int c4  = (idx & 7) * 4;
            float4 av = *(const float4*)(A + (size_t)(m0 + row) * 256 + k0 + c4);
            As[row][c4 + 0] = av.x; As[row][c4 + 1] = av.y;
            As[row][c4 + 2] = av.z; As[row][c4 + 3] = av.w;
            float4 wv = *(const float4*)(W + (size_t)(n0 + row) * 256 + k0 + c4);
            Ws[row][c4 + 0] = wv.x; Ws[row][c4 + 1] = wv.y;
            Ws[row][c4 + 2] = wv.z; Ws[row][c4 + 3] = wv.w;
        }
        __syncthreads();

        #pragma unroll 8
        for (int kk = 0; kk < 32; ++kk) {
            float a[4], w[4];
            #pragma unroll
            for (int i = 0; i < 4; ++i) a[i] = As[ty + 16 * i][kk];
            #pragma unroll
            for (int j = 0; j < 4; ++j) w[j] = Ws[tx + 16 * j][kk];
            #pragma unroll
            for (int i = 0; i < 4; ++i)
                #pragma unroll
                for (int j = 0; j < 4; ++j)
                    acc[i][j] += a[i] * w[j];
        }
        __syncthreads();
    }

    #pragma unroll
    for (int i = 0; i < 4; ++i) {
        int m = m0 + ty + 16 * i;
        #pragma unroll
        for (int j = 0; j < 4; ++j) {
            int n = n0 + tx + 16 * j;
            float c = acc[i][j];
            if (bias) c += bias[n];
            C[(size_t)m * 256 + n] = c;
        }
    }
}

// ---------------------------------------------------------------------------
// Tensor-core helpers
// ---------------------------------------------------------------------------
__device__ __forceinline__ void mma16816(float d[4], const unsigned a[4],
                                         unsigned b0, unsigned b1)
{
    asm volatile(
        "mma.sync.aligned.m16n8k16.row.col.f32.bf16.bf16.f32 "
        "{%0,%1,%2,%3},{%4,%5,%6,%7},{%8,%9},{%0,%1,%2,%3};\n"
        : "+f"(d[0]), "+f"(d[1]), "+f"(d[2]), "+f"(d[3])
        : "r"(a[0]), "r"(a[1]), "r"(a[2]), "r"(a[3]), "r"(b0), "r"(b1));
}

__device__ __forceinline__ void ldsm4(unsigned &r0, unsigned &r1,
                                      unsigned &r2, unsigned &r3, unsigned addr)
{
    asm volatile("ldmatrix.sync.aligned.m8n8.x4.shared.b16 {%0,%1,%2,%3}, [%4];\n"
        : "=r"(r0), "=r"(r1), "=r"(r2), "=r"(r3) : "r"(addr));
}

__device__ __forceinline__ void ldsm4t(unsigned &r0, unsigned &r1,
                                       unsigned &r2, unsigned &r3, unsigned addr)
{
    asm volatile("ldmatrix.sync.aligned.m8n8.x4.trans.shared.b16 {%0,%1,%2,%3}, [%4];\n"
        : "=r"(r0), "=r"(r1), "=r"(r2), "=r"(r3) : "r"(addr));
}

// split two fp32 into (hi, lo) bf16x2 packed registers (x -> low half)
__device__ __forceinline__ void split2(float x, float y, unsigned &hi, unsigned &lo)
{
    __nv_bfloat16 hx = __float2bfloat16(x);
    __nv_bfloat16 hy = __float2bfloat16(y);
    float rx = x - __bfloat162float(hx);
    float ry = y - __bfloat162float(hy);
    __nv_bfloat162 hv = __halves2bfloat162(hx, hy);
    __nv_bfloat162 lv = __halves2bfloat162(__float2bfloat16(rx), __float2bfloat16(ry));
    hi = *reinterpret_cast<unsigned*>(&hv);
    lo = *reinterpret_cast<unsigned*>(&lv);
}

// split a float4 and store hi/lo bf16 pairs into smem
__device__ __forceinline__ void split_store4(float4 v, __nv_bfloat16* hp, __nv_bfloat16* lp)
{
    unsigned h01, l01, h23, l23;
    split2(v.x, v.y, h01, l01);
    split2(v.z, v.w, h23, l23);
    *reinterpret_cast<unsigned*>(hp)     = h01;
    *reinterpret_cast<unsigned*>(hp + 2) = h23;
    *reinterpret_cast<unsigned*>(lp)     = l01;
    *reinterpret_cast<unsigned*>(lp + 2) = l23;
}

// ---------------------------------------------------------------------------
// Fused masked flash-attention via bf16-split tensor-core MMA.
// Grid: (N/128, H, B). Block: 256 threads = 8 warps.
// Warp w owns 16 query rows (q0 + 16w .. +15).
// S = (Qhi+Qlo)(Khi+Klo)^T via 3 mmas; softmax without max-tracking
// (scores bounded ~|s|<10): p = adj * exp(s), deferred row-sum normalize.
// P repacked in registers (C-frag -> A-frag), PV also 3-mma split.
// ---------------------------------------------------------------------------
__global__ __launch_bounds__(256, 1) void attn_mma(const float* __restrict__ adj)
{
    __shared__ __align__(16) __nv_bfloat16 skv[4 * 128 * KS];   // 40 KB
    __nv_bfloat16* Khi = skv;
    __nv_bfloat16* Klo = skv + 128 * KS;
    __nv_bfloat16* Vhi = skv + 2 * 128 * KS;
    __nv_bfloat16* Vlo = skv + 3 * 128 * KS;

    const int t    = threadIdx.x;
    const int w    = t >> 5;
    const int lane = t & 31;
    const int r    = lane >> 2;          // 0..7
    const int c2   = (lane & 3) * 2;     // col-pair base
    const int q0   = blockIdx.x * 128;
    const int h    = blockIdx.y;
    const int b    = blockIdx.z;

    const float qscale = 0.17677669529663687f;  // 1/sqrt(32)
    const float* Qg = g_Q + ((size_t)b * NN + q0 + 16 * w) * DM + h * DHD;
    const float* Kg = g_K + (size_t)b * NN * DM + h * DHD;
    const float* Vg = g_V + (size_t)b * NN * DM + h * DHD;
    const float* adjr0 = adj + (size_t)b * NN * NN + (size_t)(q0 + 16 * w + r) * NN + c2;
    const float* adjr1 = adjr0 + 8 * NN;

    const unsigned sb  = (unsigned)__cvta_generic_to_shared(skv);
    const unsigned KHI = sb;
    const unsigned KLO = sb + 128 * KS * 2;
    const unsigned VHI = sb + 2 * 128 * KS * 2;
    const unsigned VLO = sb + 3 * 128 * KS * 2;

    // --- Q fragments (held in registers all kernel) ---
    unsigned qh[2][4], ql[2][4];
    #pragma unroll
    for (int kc = 0; kc < 2; ++kc)
        #pragma unroll
        for (int i = 0; i < 4; ++i) {
            int ro = (i & 1) * 8;
            int co = (i >> 1) * 8;
            float2 v = *(const float2*)(Qg + (size_t)(r + ro) * DM + kc * 16 + co + c2);
            v.x *= qscale; v.y *= qscale;
            split2(v.x, v.y, qh[kc][i], ql[kc][i]);
        }

    float dacc[4][4];
    #pragma unroll
    for (int i = 0; i < 4; ++i)
        #pragma unroll
        for (int j = 0; j < 4; ++j) dacc[i][j] = 0.0f;
    float lsum0 = 0.0f, lsum1 = 0.0f;

    for (int m0 = 0; m0 < NN; m0 += 128) {
        __syncthreads();   // previous tile consumed

        // --- stage K/V tile, split to hi/lo bf16 ---
        #pragma unroll
        for (int i = 0; i < 4; ++i) {
            int e   = t + i * 256;        // 0..1023 float4 slots (128 rows x 8)
            int row = e >> 3;
            int c4  = (e & 7) * 4;
            float4 kv = *(const float4*)(Kg + (size_t)(m0 + row) * DM + c4);
            split_store4(kv, Khi + row * KS + c4, Klo + row * KS + c4);
            float4 vv = *(const float4*)(Vg + (size_t)(m0 + row) * DM + c4);
            split_store4(vv, Vhi + row * KS + c4, Vlo + row * KS + c4);
        }
        __syncthreads();

        // --- S = Q K^T (16 x 128 per warp), 3-mma bf16 split ---
        float s[16][4];
        #pragma unroll
        for (int j = 0; j < 16; ++j)
            #pragma unroll
            for (int i = 0; i < 4; ++i) s[j][i] = 0.0f;

        #pragma unroll
        for (int kc = 0; kc < 2; ++kc) {
            #pragma unroll
            for (int np = 0; np < 8; ++np) {
                int row = np * 16 + (lane & 7) + ((lane & 16) ? 8 : 0);
                int col = kc * 16 + ((lane & 8) ? 8 : 0);
                unsigned b0, b1, b2, b3;
                ldsm4(b0, b1, b2, b3, KHI + (row * KS + col) * 2);
                mma16816(s[2 * np],     qh[kc], b0, b1);
                mma16816(s[2 * np + 1], qh[kc], b2, b3);
                mma16816(s[2 * np],     ql[kc], b0, b1);
                mma16816(s[2 * np + 1], ql[kc], b2, b3);
                unsigned l0, l1, l2, l3;
                ldsm4(l0, l1, l2, l3, KLO + (row * KS + col) * 2);
                mma16816(s[2 * np],     qh[kc], l0, l1);
                mma16816(s[2 * np + 1], qh[kc], l2, l3);
            }
        }

        // --- mask * exp, accumulate row sums, repack C-frag -> A-frag ---
        unsigned pah[8][4], pal[8][4];
        #pragma unroll
        for (int j = 0; j < 16; ++j) {
            float2 a0 = *(const float2*)(adjr0 + m0 + 8 * j);
            float2 a1 = *(const float2*)(adjr1 + m0 + 8 * j);
            float p00 = a0.x * __expf(s[j][0]);
            float p01 = a0.y * __expf(s[j][1]);
            float p10 = a1.x * __expf(s[j][2]);
            float p11 = a1.y * __expf(s[j][3]);
            lsum0 += p00 + p01;
            lsum1 += p10 + p11;
            unsigned h0, l0u, h1, l1u;
            split2(p00, p01, h0, l0u);
            split2(p10, p11, h1, l1u);
            int tt = j >> 1, o = (j & 1) * 2;
            pah[tt][o]     = h0;
            pah[tt][o + 1] = h1;
            pal[tt][o]     = l0u;
            pal[tt][o + 1] = l1u;
        }

        // --- acc += P V (16 x 32 per warp), 3-mma bf16 split ---
        #pragma unroll
        for (int kt = 0; kt < 8; ++kt) {
            int row  = kt * 16 + (lane & 7) + ((lane & 8) ? 8 : 0);
            int colA = (lane & 16) ? 8 : 0;
            unsigned vh0, vh1, vh2, vh3, vl0, vl1, vl2, vl3;
            ldsm4t(vh0, vh1, vh2, vh3, VHI + (row * KS + colA) * 2);
            ldsm4t(vl0, vl1, vl2, vl3, VLO + (row * KS + colA) * 2);
            mma16816(dacc[0], pah[kt], vh0, vh1);
            mma16816(dacc[1], pah[kt], vh2, vh3);
            mma16816(dacc[0], pal[kt], vh0, vh1);
            mma16816(dacc[1], pal[kt], vh2, vh3);
            mma16816(dacc[0], pah[kt], vl0, vl1);
            mma16816(dacc[1], pah[kt], vl2, vl3);
            ldsm4t(vh0, vh1, vh2, vh3, VHI + (row * KS + colA + 16) * 2);
            ldsm4t(vl0, vl1, vl2, vl3, VLO + (row * KS + colA + 16) * 2);
            mma16816(dacc[2], pah[kt], vh0, vh1);
            mma16816(dacc[3], pah[kt], vh2, vh3);
            mma16816(dacc[2], pal[kt], vh0, vh1);
            mma16816(dacc[3], pal[kt], vh2, vh3);
            mma16816(dacc[2], pah[kt], vl0, vl1);
            mma16816(dacc[3], pah[kt], vl2, vl3);
        }
    }

    // --- final row-sum reduction (lanes sharing a row: xor 1, 2) + write ---
    lsum0 += __shfl_xor_sync(0xffffffffu, lsum0, 1);
    lsum0 += __shfl_xor_sync(0xffffffffu, lsum0, 2);
    lsum1 += __shfl_xor_sync(0xffffffffu, lsum1, 1);
    lsum1 += __shfl_xor_sync(0xffffffffu, lsum1, 2);
    float inv0 = 1.0f / lsum0;
    float inv1 = 1.0f / lsum1;

    float* og = g_A + ((size_t)b * NN + q0 + 16 * w) * DM + h * DHD;
    #pragma unroll
    for (int nd = 0; nd < 4; ++nd) {
        float2 o0 = make_float2(dacc[nd][0] * inv0, dacc[nd][1] * inv0);
        float2 o1 = make_float2(dacc[nd][2] * inv1, dacc[nd][3] * inv1);
        *(float2*)(og + (size_t)r * DM + nd * 8 + c2)       = o0;
        *(float2*)(og + (size_t)(r + 8) * DM + nd * 8 + c2) = o1;
    }
}

// ---------------------------------------------------------------------------
// Launch
// ---------------------------------------------------------------------------
extern "C" void kernel_launch(void* const* d_in, const int* in_sizes, int n_in,
                              void* d_out, int out_size)
{
    const float* x   = (const float*)d_in[0];
    const float* adj = (const float*)d_in[1];
    const float* Wq  = (const float*)d_in[2];
    const float* Wk  = (const float*)d_in[3];
    const float* Wv  = (const float*)d_in[4];
    const float* Wo  = (const float*)d_in[5];
    const float* bo  = (const float*)d_in[6];
    float* out = (float*)d_out;

    float *Qp, *Kp, *Vp, *Ap;
    cudaGetSymbolAddress((void**)&Qp, g_Q);
    cudaGetSymbolAddress((void**)&Kp, g_K);
    cudaGetSymbolAddress((void**)&Vp, g_V);
    cudaGetSymbolAddress((void**)&Ap, g_A);

    dim3 ggemm(64, 4);   // M=4096/64, N=256/64
    gemm_xwT<<<ggemm, 256>>>(x, Wq, nullptr, Qp);
    gemm_xwT<<<ggemm, 256>>>(x, Wk, nullptr, Kp);
    gemm_xwT<<<ggemm, 256>>>(x, Wv, nullptr, Vp);

    attn_mma<<<dim3(NN / 128, HH, BB), 256>>>(adj);

    gemm_xwT<<<ggemm, 256>>>(Ap, Wo, bo, out);
}

// round 11
// speedup vs baseline: 2.7569x; 1.3027x over previous
#include <cuda_runtime.h>
#include <cuda_bf16.h>
#include <math.h>

// Problem constants
#define BB 2
#define NN 2048
#define DM 256     // d_model = H*DH
#define HH 8
#define DHD 32
#define KS 40      // attn smem row stride (bf16): 80B -> conflict-free ldmatrix
#define GS 72      // gemm smem row stride (bf16): 144B -> conflict-free ldmatrix

// ---------------------------------------------------------------------------
// Scratch (device globals: no allocations allowed)
// ---------------------------------------------------------------------------
__device__ __nv_bfloat16 g_xh[BB * NN * DM];          // x split hi
__device__ __nv_bfloat16 g_xl[BB * NN * DM];          // x split lo
__device__ __nv_bfloat16 g_wh[4 * DM * DM];           // Wq,Wk,Wv,Wo split hi
__device__ __nv_bfloat16 g_wl[4 * DM * DM];
__device__ __nv_bfloat16 g_ph[3 * BB * NN * DM];      // Q(scaled),K,V split hi
__device__ __nv_bfloat16 g_pl[3 * BB * NN * DM];
__device__ __nv_bfloat16 g_ah[BB * NN * DM];          // attn out split hi
__device__ __nv_bfloat16 g_al[BB * NN * DM];
__device__ unsigned      g_adjb[BB * NN * (NN / 32)]; // adjacency bitmask

// ---------------------------------------------------------------------------
// Helpers
// ---------------------------------------------------------------------------
__device__ __forceinline__ void mma16816(float d[4], const unsigned a[4],
                                         unsigned b0, unsigned b1)
{
    asm volatile(
        "mma.sync.aligned.m16n8k16.row.col.f32.bf16.bf16.f32 "
        "{%0,%1,%2,%3},{%4,%5,%6,%7},{%8,%9},{%0,%1,%2,%3};\n"
        : "+f"(d[0]), "+f"(d[1]), "+f"(d[2]), "+f"(d[3])
        : "r"(a[0]), "r"(a[1]), "r"(a[2]), "r"(a[3]), "r"(b0), "r"(b1));
}

__device__ __forceinline__ void ldsm4(unsigned &r0, unsigned &r1,
                                      unsigned &r2, unsigned &r3, unsigned addr)
{
    asm volatile("ldmatrix.sync.aligned.m8n8.x4.shared.b16 {%0,%1,%2,%3}, [%4];\n"
        : "=r"(r0), "=r"(r1), "=r"(r2), "=r"(r3) : "r"(addr));
}

__device__ __forceinline__ void ldsm4t(unsigned &r0, unsigned &r1,
                                       unsigned &r2, unsigned &r3, unsigned addr)
{
    asm volatile("ldmatrix.sync.aligned.m8n8.x4.trans.shared.b16 {%0,%1,%2,%3}, [%4];\n"
        : "=r"(r0), "=r"(r1), "=r"(r2), "=r"(r3) : "r"(addr));
}

// split two fp32 into (hi, lo) bf16x2 packed registers (x -> low half)
__device__ __forceinline__ void split2(float x, float y, unsigned &hi, unsigned &lo)
{
    __nv_bfloat16 hx = __float2bfloat16(x);
    __nv_bfloat16 hy = __float2bfloat16(y);
    float rx = x - __bfloat162float(hx);
    float ry = y - __bfloat162float(hy);
    __nv_bfloat162 hv = __halves2bfloat162(hx, hy);
    __nv_bfloat162 lv = __halves2bfloat162(__float2bfloat16(rx), __float2bfloat16(ry));
    hi = *reinterpret_cast<unsigned*>(&hv);
    lo = *reinterpret_cast<unsigned*>(&lv);
}

__device__ __forceinline__ void split_store4(float4 v, __nv_bfloat16* hp, __nv_bfloat16* lp)
{
    unsigned h01, l01, h23, l23;
    split2(v.x, v.y, h01, l01);
    split2(v.z, v.w, h23, l23);
    *reinterpret_cast<unsigned*>(hp)     = h01;
    *reinterpret_cast<unsigned*>(hp + 2) = h23;
    *reinterpret_cast<unsigned*>(lp)     = l01;
    *reinterpret_cast<unsigned*>(lp + 2) = l23;
}

__device__ __forceinline__ void cp_async16(unsigned dst, const void* src)
{
    asm volatile("cp.async.cg.shared.global [%0], [%1], 16;\n" :: "r"(dst), "l"(src));
}

// ---------------------------------------------------------------------------
// Prep kernels
// ---------------------------------------------------------------------------
__global__ __launch_bounds__(256) void split_x_kernel(const float* __restrict__ src)
{
    int i = blockIdx.x * 256 + threadIdx.x;             // over 262144 float4
    float4 v = ((const float4*)src)[i];
    split_store4(v, g_xh + i * 4, g_xl + i * 4);
}

__global__ __launch_bounds__(256) void split_w_kernel(
    const float* __restrict__ wq, const float* __restrict__ wk,
    const float* __restrict__ wv, const float* __restrict__ wo)
{
    int i = blockIdx.x * 256 + threadIdx.x;             // over 65536 float4
    int seg = i >> 14;                                   // 16384 float4 per weight
    int off = i & 16383;
    const float* src = (seg == 0) ? wq : (seg == 1) ? wk : (seg == 2) ? wv : wo;
    float4 v = ((const float4*)src)[off];
    split_store4(v, g_wh + (size_t)seg * DM * DM + off * 4,
                    g_wl + (size_t)seg * DM * DM + off * 4);
}

__global__ __launch_bounds__(256) void adj_bits_kernel(const float* __restrict__ adj)
{
    int gw   = (blockIdx.x * 256 + threadIdx.x) >> 5;   // 8192 warps
    int lane = threadIdx.x & 31;
    size_t base = (size_t)gw * 1024;
    unsigned my = 0;
    #pragma unroll 8
    for (int k = 0; k < 32; ++k) {
        float v = adj[base + (size_t)k * 32 + lane];
        unsigned word = __ballot_sync(0xffffffffu, v != 0.0f);
        if (lane == k) my = word;
    }
    g_adjb[(size_t)gw * 32 + lane] = my;
}

// ---------------------------------------------------------------------------
// bf16-split tensor-core GEMM: C[4096 x 256] = A @ W^T
// Block 128x64, 8 warps (warp: 16 rows x 64 cols). K = 256 in 4 stages of 64.
// blockIdx.z selects weight segment / output segment.
// If Of != nullptr: fp32 output + bias. Else: split bf16 out (scale0 on z==0).
// ---------------------------------------------------------------------------
__global__ __launch_bounds__(256) void gemm_split(
    const __nv_bfloat16* __restrict__ Ah, const __nv_bfloat16* __restrict__ Al,
    const __nv_bfloat16* __restrict__ Whb, const __nv_bfloat16* __restrict__ Wlb,
    __nv_bfloat16* __restrict__ Ohb, __nv_bfloat16* __restrict__ Olb,
    float* __restrict__ Of, const float* __restrict__ bias, float scale0)
{
    extern __shared__ __align__(16) __nv_bfloat16 sg[];
    __nv_bfloat16* sAh = sg;                 // 128*GS
    __nv_bfloat16* sAl = sg + 128 * GS;
    __nv_bfloat16* sWh = sg + 2 * 128 * GS;  // 64*GS
    __nv_bfloat16* sWl = sg + 2 * 128 * GS + 64 * GS;

    const int z = blockIdx.z;
    const __nv_bfloat16* Wh = Whb + (size_t)z * DM * DM;
    const __nv_bfloat16* Wl = Wlb + (size_t)z * DM * DM;

    const int t = threadIdx.x, w = t >> 5, lane = t & 31;
    const int m0 = blockIdx.x * 128, n0 = blockIdx.y * 64;

    const unsigned sb  = (unsigned)__cvta_generic_to_shared(sg);
    const unsigned SAH = sb;
    const unsigned SAL = sb + 128 * GS * 2;
    const unsigned SWH = sb + 2 * 128 * GS * 2;
    const unsigned SWL = SWH + 64 * GS * 2;

    float acc[8][4];
    #pragma unroll
    for (int i = 0; i < 8; ++i)
        #pragma unroll
        for (int j = 0; j < 4; ++j) acc[i][j] = 0.0f;

    for (int s = 0; s < 4; ++s) {
        const int k0 = s * 64;
        __syncthreads();
        // stage A tiles (hi+lo): 2048 uint4 / 256 thr = 8
        #pragma unroll
        for (int i = 0; i < 8; ++i) {
            int idx = t + i * 256;
            int buf = idx >> 10;
            int rem = idx & 1023;
            int row = rem >> 3, ch = rem & 7;
            const __nv_bfloat16* src = (buf ? Al : Ah) + (size_t)(m0 + row) * DM + k0 + ch * 8;
            __nv_bfloat16* dst = (buf ? sAl : sAh) + row * GS + ch * 8;
            *(uint4*)dst = *(const uint4*)src;
        }
        // stage W tiles: 1024 uint4 / 256 = 4
        #pragma unroll
        for (int i = 0; i < 4; ++i) {
            int idx = t + i * 256;
            int buf = idx >> 9;
            int rem = idx & 511;
            int row = rem >> 3, ch = rem & 7;
            const __nv_bfloat16* src = (buf ? Wl : Wh) + (size_t)(n0 + row) * DM + k0 + ch * 8;
            __nv_bfloat16* dst = (buf ? sWl : sWh) + row * GS + ch * 8;
            *(uint4*)dst = *(const uint4*)src;
        }
        __syncthreads();

        #pragma unroll
        for (int ks = 0; ks < 4; ++ks) {
            unsigned ah[4], al[4];
            int arow = 16 * w + (lane & 15);
            int acol = ks * 16 + ((lane & 16) ? 8 : 0);
            ldsm4(ah[0], ah[1], ah[2], ah[3], SAH + (arow * GS + acol) * 2);
            ldsm4(al[0], al[1], al[2], al[3], SAL + (arow * GS + acol) * 2);
            #pragma unroll
            for (int np = 0; np < 4; ++np) {
                int brow = np * 16 + (lane & 7) + ((lane & 16) ? 8 : 0);
                int bcol = ks * 16 + ((lane & 8) ? 8 : 0);
                unsigned bh0, bh1, bh2, bh3, bl0, bl1, bl2, bl3;
                ldsm4(bh0, bh1, bh2, bh3, SWH + (brow * GS + bcol) * 2);
                mma16816(acc[2 * np],     ah, bh0, bh1);
                mma16816(acc[2 * np + 1], ah, bh2, bh3);
                mma16816(acc[2 * np],     al, bh0, bh1);
                mma16816(acc[2 * np + 1], al, bh2, bh3);
                ldsm4(bl0, bl1, bl2, bl3, SWL + (brow * GS + bcol) * 2);
                mma16816(acc[2 * np],     ah, bl0, bl1);
                mma16816(acc[2 * np + 1], ah, bl2, bl3);
            }
        }
    }

    const int r = lane >> 2, c2 = (lane & 3) * 2;
    const int row0 = m0 + 16 * w + r;
    if (Of) {
        #pragma unroll
        for (int j = 0; j < 8; ++j) {
            int col = n0 + 8 * j + c2;
            float b0v = bias[col], b1v = bias[col + 1];
            *(float2*)(Of + (size_t)row0 * DM + col) =
                make_float2(acc[j][0] + b0v, acc[j][1] + b1v);
            *(float2*)(Of + (size_t)(row0 + 8) * DM + col) =
                make_float2(acc[j][2] + b0v, acc[j][3] + b1v);
        }
    } else {
        const float sc = (z == 0) ? scale0 : 1.0f;
        __nv_bfloat16* Oh = Ohb + (size_t)z * BB * NN * DM;
        __nv_bfloat16* Ol = Olb + (size_t)z * BB * NN * DM;
        #pragma unroll
        for (int j = 0; j < 8; ++j) {
            int col = n0 + 8 * j + c2;
            unsigned h0, l0, h1, l1;
            split2(acc[j][0] * sc, acc[j][1] * sc, h0, l0);
            split2(acc[j][2] * sc, acc[j][3] * sc, h1, l1);
            *(unsigned*)(Oh + (size_t)row0 * DM + col)       = h0;
            *(unsigned*)(Ol + (size_t)row0 * DM + col)       = l0;
            *(unsigned*)(Oh + (size_t)(row0 + 8) * DM + col) = h1;
            *(unsigned*)(Ol + (size_t)(row0 + 8) * DM + col) = l1;
        }
    }
}

// ---------------------------------------------------------------------------
// Fused masked attention, bf16-split MMA, cp.async double-buffered K/V,
// bitmask adjacency. Grid (16, H, B), 256 threads = 8 warps.
// ---------------------------------------------------------------------------
#define STAGE_B (4 * 128 * KS * 2)   // bytes per stage (Kh,Kl,Vh,Vl)
#define BUF_B   (128 * KS * 2)

__global__ __launch_bounds__(256, 1) void attn_mma(int dummy)
{
    extern __shared__ __align__(16) __nv_bfloat16 skv[];  // 2 stages

    const int t    = threadIdx.x;
    const int w    = t >> 5;
    const int lane = t & 31;
    const int r    = lane >> 2;
    const int c2   = (lane & 3) * 2;
    const int q0   = blockIdx.x * 128;
    const int h    = blockIdx.y;
    const int b    = blockIdx.z;

    const __nv_bfloat16* Qh = g_ph + ((size_t)b * NN + q0 + 16 * w) * DM + h * DHD;
    const __nv_bfloat16* Ql = g_pl + ((size_t)b * NN + q0 + 16 * w) * DM + h * DHD;
    const __nv_bfloat16* srcb[4] = {
        g_ph + ((size_t)(BB + b) * NN) * DM + h * DHD,        // K hi (segment 1)
        g_pl + ((size_t)(BB + b) * NN) * DM + h * DHD,        // K lo
        g_ph + ((size_t)(2 * BB + b) * NN) * DM + h * DHD,    // V hi (segment 2)
        g_pl + ((size_t)(2 * BB + b) * NN) * DM + h * DHD     // V lo
    };
    const unsigned* abr0 = g_adjb + ((size_t)b * NN + q0 + 16 * w + r) * (NN / 32);
    const unsigned* abr1 = abr0 + 8 * (NN / 32);

    const unsigned sb = (unsigned)__cvta_generic_to_shared(skv);

    // --- Q fragments from global (pre-scaled, pre-split) ---
    unsigned qh[2][4], ql[2][4];
    #pragma unroll
    for (int kc = 0; kc < 2; ++kc)
        #pragma unroll
        for (int i = 0; i < 4; ++i) {
            int off = (size_t)0;
            int ro = (i & 1) * 8;
            int co = (i >> 1) * 8;
            qh[kc][i] = *(const unsigned*)(Qh + (size_t)(r + ro) * DM + kc * 16 + co + c2);
            ql[kc][i] = *(const unsigned*)(Ql + (size_t)(r + ro) * DM + kc * 16 + co + c2);
            (void)off;
        }

    float dacc[4][4];
    #pragma unroll
    for (int i = 0; i < 4; ++i)
        #pragma unroll
        for (int j = 0; j < 4; ++j) dacc[i][j] = 0.0f;
    float lsum0 = 0.0f, lsum1 = 0.0f;

    // --- cp.async stage issue: 2048 x 16B per tile / 256 thr = 8 each ---
    auto issue_tile = [&](int tt) {
        const int stage = tt & 1;
        const int m0 = tt * 128;
        const unsigned dstbase = sb + stage * STAGE_B;
        #pragma unroll
        for (int i = 0; i < 8; ++i) {
            int idx = t + i * 256;
            int buf = idx >> 9;
            int rem = idx & 511;
            int row = rem >> 2;
            int ch  = rem & 3;
            const __nv_bfloat16* src = srcb[buf] + (size_t)(m0 + row) * DM + ch * 8;
            cp_async16(dstbase + buf * BUF_B + row * (KS * 2) + ch * 16, src);
        }
    };

    issue_tile(0);
    asm volatile("cp.async.commit_group;\n");

    for (int tt = 0; tt < NN / 128; ++tt) {
        const int m0 = tt * 128;
        if (tt + 1 < NN / 128) {
            issue_tile(tt + 1);
            asm volatile("cp.async.commit_group;\n");
            asm volatile("cp.async.wait_group 1;\n");
        } else {
            asm volatile("cp.async.wait_group 0;\n");
        }
        __syncthreads();

        const unsigned st  = sb + (tt & 1) * STAGE_B;
        const unsigned KHI = st;
        const unsigned KLO = st + BUF_B;
        const unsigned VHI = st + 2 * BUF_B;
        const unsigned VLO = st + 3 * BUF_B;

        // prefetch mask words (hide latency behind QK mmas)
        uint4 mv0 = *(const uint4*)(abr0 + (m0 >> 5));
        uint4 mv1 = *(const uint4*)(abr1 + (m0 >> 5));
        unsigned mw0[4] = {mv0.x, mv0.y, mv0.z, mv0.w};
        unsigned mw1[4] = {mv1.x, mv1.y, mv1.z, mv1.w};

        // --- S = Q K^T ---
        float s[16][4];
        #pragma unroll
        for (int j = 0; j < 16; ++j)
            #pragma unroll
            for (int i = 0; i < 4; ++i) s[j][i] = 0.0f;

        #pragma unroll
        for (int kc = 0; kc < 2; ++kc) {
            #pragma unroll
            for (int np = 0; np < 8; ++np) {
                int row = np * 16 + (lane & 7) + ((lane & 16) ? 8 : 0);
                int col = kc * 16 + ((lane & 8) ? 8 : 0);
                unsigned b0, b1, b2, b3;
                ldsm4(b0, b1, b2, b3, KHI + (row * KS + col) * 2);
                mma16816(s[2 * np],     qh[kc], b0, b1);
                mma16816(s[2 * np + 1], qh[kc], b2, b3);
                mma16816(s[2 * np],     ql[kc], b0, b1);
                mma16816(s[2 * np + 1], ql[kc], b2, b3);
                unsigned l0, l1, l2, l3;
                ldsm4(l0, l1, l2, l3, KLO + (row * KS + col) * 2);
                mma16816(s[2 * np],     qh[kc], l0, l1);
                mma16816(s[2 * np + 1], qh[kc], l2, l3);
            }
        }

        // --- mask(bit) * exp, row sums, repack C-frag -> A-frag ---
        unsigned pah[8][4], pal[8][4];
        #pragma unroll
        for (int j = 0; j < 16; ++j) {
            int bit = (8 * j + c2) & 31;
            unsigned w0 = mw0[j >> 2], w1 = mw1[j >> 2];
            float p00 = ((w0 >> bit) & 1)       ? __expf(s[j][0]) : 0.0f;
            float p01 = ((w0 >> (bit + 1)) & 1) ? __expf(s[j][1]) : 0.0f;
            float p10 = ((w1 >> bit) & 1)       ? __expf(s[j][2]) : 0.0f;
            float p11 = ((w1 >> (bit + 1)) & 1) ? __expf(s[j][3]) : 0.0f;
            lsum0 += p00 + p01;
            lsum1 += p10 + p11;
            unsigned h0, l0u, h1, l1u;
            split2(p00, p01, h0, l0u);
            split2(p10, p11, h1, l1u);
            int tti = j >> 1, o = (j & 1) * 2;
            pah[tti][o]     = h0;
            pah[tti][o + 1] = h1;
            pal[tti][o]     = l0u;
            pal[tti][o + 1] = l1u;
        }

        // --- acc += P V ---
        #pragma unroll
        for (int kt = 0; kt < 8; ++kt) {
            int row  = kt * 16 + (lane & 7) + ((lane & 8) ? 8 : 0);
            int colA = (lane & 16) ? 8 : 0;
            unsigned vh0, vh1, vh2, vh3, vl0, vl1, vl2, vl3;
            ldsm4t(vh0, vh1, vh2, vh3, VHI + (row * KS + colA) * 2);
            ldsm4t(vl0, vl1, vl2, vl3, VLO + (row * KS + colA) * 2);
            mma16816(dacc[0], pah[kt], vh0, vh1);
            mma16816(dacc[1], pah[kt], vh2, vh3);
            mma16816(dacc[0], pal[kt], vh0, vh1);
            mma16816(dacc[1], pal[kt], vh2, vh3);
            mma16816(dacc[0], pah[kt], vl0, vl1);
            mma16816(dacc[1], pah[kt], vl2, vl3);
            ldsm4t(vh0, vh1, vh2, vh3, VHI + (row * KS + colA + 16) * 2);
            ldsm4t(vl0, vl1, vl2, vl3, VLO + (row * KS + colA + 16) * 2);
            mma16816(dacc[2], pah[kt], vh0, vh1);
            mma16816(dacc[3], pah[kt], vh2, vh3);
            mma16816(dacc[2], pal[kt], vh0, vh1);
            mma16816(dacc[3], pal[kt], vh2, vh3);
            mma16816(dacc[2], pah[kt], vl0, vl1);
            mma16816(dacc[3], pah[kt], vl2, vl3);
        }
        __syncthreads();   // all warps done reading this stage before reuse
    }

    // --- row-sum reduce (lanes xor 1,2 share a row) + split write ---
    lsum0 += __shfl_xor_sync(0xffffffffu, lsum0, 1);
    lsum0 += __shfl_xor_sync(0xffffffffu, lsum0, 2);
    lsum1 += __shfl_xor_sync(0xffffffffu, lsum1, 1);
    lsum1 += __shfl_xor_sync(0xffffffffu, lsum1, 2);
    float inv0 = 1.0f / lsum0;
    float inv1 = 1.0f / lsum1;

    __nv_bfloat16* ogh = g_ah + ((size_t)b * NN + q0 + 16 * w) * DM + h * DHD;
    __nv_bfloat16* ogl = g_al + ((size_t)b * NN + q0 + 16 * w) * DM + h * DHD;
    #pragma unroll
    for (int nd = 0; nd < 4; ++nd) {
        unsigned h0, l0, h1, l1;
        split2(dacc[nd][0] * inv0, dacc[nd][1] * inv0, h0, l0);
        split2(dacc[nd][2] * inv1, dacc[nd][3] * inv1, h1, l1);
        *(unsigned*)(ogh + (size_t)r * DM + nd * 8 + c2)       = h0;
        *(unsigned*)(ogl + (size_t)r * DM + nd * 8 + c2)       = l0;
        *(unsigned*)(ogh + (size_t)(r + 8) * DM + nd * 8 + c2) = h1;
        *(unsigned*)(ogl + (size_t)(r + 8) * DM + nd * 8 + c2) = l1;
    }
}

// ---------------------------------------------------------------------------
// Launch
// ---------------------------------------------------------------------------
extern "C" void kernel_launch(void* const* d_in, const int* in_sizes, int n_in,
                              void* d_out, int out_size)
{
    const float* x   = (const float*)d_in[0];
    const float* adj = (const float*)d_in[1];
    const float* Wq  = (const float*)d_in[2];
    const float* Wk  = (const float*)d_in[3];
    const float* Wv  = (const float*)d_in[4];
    const float* Wo  = (const float*)d_in[5];
    const float* bo  = (const float*)d_in[6];
    float* out = (float*)d_out;

    __nv_bfloat16 *xh, *xl, *wh, *wl, *ph, *pl, *ah, *al;
    cudaGetSymbolAddress((void**)&xh, g_xh);
    cudaGetSymbolAddress((void**)&xl, g_xl);
    cudaGetSymbolAddress((void**)&wh, g_wh);
    cudaGetSymbolAddress((void**)&wl, g_wl);
    cudaGetSymbolAddress((void**)&ph, g_ph);
    cudaGetSymbolAddress((void**)&pl, g_pl);
    cudaGetSymbolAddress((void**)&ah, g_ah);
    cudaGetSymbolAddress((void**)&al, g_al);

    const int gemm_smem = (2 * 128 * GS + 2 * 64 * GS) * (int)sizeof(__nv_bfloat16); // 55296
    const int attn_smem = 2 * STAGE_B;                                                // 81920
    cudaFuncSetAttribute(gemm_split, cudaFuncAttributeMaxDynamicSharedMemorySize, gemm_smem);
    cudaFuncSetAttribute(attn_mma,   cudaFuncAttributeMaxDynamicSharedMemorySize, attn_smem);

    // prep
    split_x_kernel<<<1024, 256>>>(x);
    split_w_kernel<<<256, 256>>>(Wq, Wk, Wv, Wo);
    adj_bits_kernel<<<1024, 256>>>(adj);

    // QKV projections (z = 0,1,2), Q pre-scaled by 1/sqrt(dh)
    gemm_split<<<dim3(32, 4, 3), 256, gemm_smem>>>(
        xh, xl, wh, wl, ph, pl, nullptr, nullptr, 0.17677669529663687f);

    // attention
    attn_mma<<<dim3(NN / 128, HH, BB), 256, attn_smem>>>(0);

    // output projection: A @ Wo^T + bo
    gemm_split<<<dim3(32, 4, 1), 256, gemm_smem>>>(
        ah, al, wh + 3 * DM * DM, wl + 3 * DM * DM,
        nullptr, nullptr, out, bo, 1.0f);
}

// round 12
// speedup vs baseline: 3.0066x; 1.0906x over previous
#include <cuda_runtime.h>
#include <cuda_bf16.h>
#include <math.h>

// Problem constants
#define BB 2
#define NN 2048
#define DM 256     // d_model = H*DH
#define HH 8
#define DHD 32
#define KS 40      // attn smem row stride (bf16): 80B -> conflict-free ldmatrix
#define GS 72      // gemm smem row stride (bf16): 144B -> conflict-free ldmatrix

// ---------------------------------------------------------------------------
// Scratch (device globals: no allocations allowed)
// ---------------------------------------------------------------------------
__device__ __nv_bfloat16 g_xh[BB * NN * DM];          // x split hi
__device__ __nv_bfloat16 g_xl[BB * NN * DM];          // x split lo
__device__ __nv_bfloat16 g_wh[4 * DM * DM];           // Wq,Wk,Wv,Wo split hi
__device__ __nv_bfloat16 g_wl[4 * DM * DM];
__device__ __nv_bfloat16 g_ph[3 * BB * NN * DM];      // Q(scaled),K,V split hi
__device__ __nv_bfloat16 g_pl[3 * BB * NN * DM];
__device__ __nv_bfloat16 g_ah[BB * NN * DM];          // attn out split hi
__device__ __nv_bfloat16 g_al[BB * NN * DM];
__device__ unsigned      g_adjb[BB * NN * (NN / 32)]; // adjacency bitmask

// ---------------------------------------------------------------------------
// Helpers
// ---------------------------------------------------------------------------
__device__ __forceinline__ void mma16816(float d[4], const unsigned a[4],
                                         unsigned b0, unsigned b1)
{
    asm volatile(
        "mma.sync.aligned.m16n8k16.row.col.f32.bf16.bf16.f32 "
        "{%0,%1,%2,%3},{%4,%5,%6,%7},{%8,%9},{%0,%1,%2,%3};\n"
        : "+f"(d[0]), "+f"(d[1]), "+f"(d[2]), "+f"(d[3])
        : "r"(a[0]), "r"(a[1]), "r"(a[2]), "r"(a[3]), "r"(b0), "r"(b1));
}

__device__ __forceinline__ void ldsm4(unsigned &r0, unsigned &r1,
                                      unsigned &r2, unsigned &r3, unsigned addr)
{
    asm volatile("ldmatrix.sync.aligned.m8n8.x4.shared.b16 {%0,%1,%2,%3}, [%4];\n"
        : "=r"(r0), "=r"(r1), "=r"(r2), "=r"(r3) : "r"(addr));
}

__device__ __forceinline__ void ldsm4t(unsigned &r0, unsigned &r1,
                                       unsigned &r2, unsigned &r3, unsigned addr)
{
    asm volatile("ldmatrix.sync.aligned.m8n8.x4.trans.shared.b16 {%0,%1,%2,%3}, [%4];\n"
        : "=r"(r0), "=r"(r1), "=r"(r2), "=r"(r3) : "r"(addr));
}

// split two fp32 into (hi, lo) bf16x2 packed registers (x -> low half)
__device__ __forceinline__ void split2(float x, float y, unsigned &hi, unsigned &lo)
{
    __nv_bfloat16 hx = __float2bfloat16(x);
    __nv_bfloat16 hy = __float2bfloat16(y);
    float rx = x - __bfloat162float(hx);
    float ry = y - __bfloat162float(hy);
    __nv_bfloat162 hv = __halves2bfloat162(hx, hy);
    __nv_bfloat162 lv = __halves2bfloat162(__float2bfloat16(rx), __float2bfloat16(ry));
    hi = *reinterpret_cast<unsigned*>(&hv);
    lo = *reinterpret_cast<unsigned*>(&lv);
}

__device__ __forceinline__ void split_store4(float4 v, __nv_bfloat16* hp, __nv_bfloat16* lp)
{
    unsigned h01, l01, h23, l23;
    split2(v.x, v.y, h01, l01);
    split2(v.z, v.w, h23, l23);
    *reinterpret_cast<unsigned*>(hp)     = h01;
    *reinterpret_cast<unsigned*>(hp + 2) = h23;
    *reinterpret_cast<unsigned*>(lp)     = l01;
    *reinterpret_cast<unsigned*>(lp + 2) = l23;
}

__device__ __forceinline__ void cp_async16(unsigned dst, const void* src)
{
    asm volatile("cp.async.cg.shared.global [%0], [%1], 16;\n" :: "r"(dst), "l"(src));
}

// ---------------------------------------------------------------------------
// Prep kernels
// ---------------------------------------------------------------------------
__global__ __launch_bounds__(256) void split_x_kernel(const float* __restrict__ src)
{
    int i = blockIdx.x * 256 + threadIdx.x;             // over 262144 float4
    float4 v = ((const float4*)src)[i];
    split_store4(v, g_xh + i * 4, g_xl + i * 4);
}

__global__ __launch_bounds__(256) void split_w_kernel(
    const float* __restrict__ wq, const float* __restrict__ wk,
    const float* __restrict__ wv, const float* __restrict__ wo)
{
    int i = blockIdx.x * 256 + threadIdx.x;             // over 65536 float4
    int seg = i >> 14;                                   // 16384 float4 per weight
    int off = i & 16383;
    const float* src = (seg == 0) ? wq : (seg == 1) ? wk : (seg == 2) ? wv : wo;
    float4 v = ((const float4*)src)[off];
    split_store4(v, g_wh + (size_t)seg * DM * DM + off * 4,
                    g_wl + (size_t)seg * DM * DM + off * 4);
}

__global__ __launch_bounds__(256) void adj_bits_kernel(const float* __restrict__ adj)
{
    int gw   = (blockIdx.x * 256 + threadIdx.x) >> 5;   // 8192 warps
    int lane = threadIdx.x & 31;
    size_t base = (size_t)gw * 1024;
    unsigned my = 0;
    #pragma unroll 8
    for (int k = 0; k < 32; ++k) {
        float v = adj[base + (size_t)k * 32 + lane];
        unsigned word = __ballot_sync(0xffffffffu, v != 0.0f);
        if (lane == k) my = word;
    }
    g_adjb[(size_t)gw * 32 + lane] = my;
}

// ---------------------------------------------------------------------------
// bf16-split tensor-core GEMM: C[4096 x 256] = A @ W^T
// Block 128x64, 8 warps. K=256 in 4 stages of 64, cp.async depth-2 pipeline.
// blockIdx.z selects weight/output segment. Of!=null: fp32 out + bias,
// else split bf16 out (scale0 applied on z==0).
// ---------------------------------------------------------------------------
#define GA_ELEM (128 * GS)                 // one A buffer (bf16 elems)
#define GW_ELEM (64 * GS)
#define GSTAGE_ELEM (2 * GA_ELEM + 2 * GW_ELEM)
#define GSTAGE_B (GSTAGE_ELEM * 2)

__global__ __launch_bounds__(256, 2) void gemm_split(
    const __nv_bfloat16* __restrict__ Ah, const __nv_bfloat16* __restrict__ Al,
    const __nv_bfloat16* __restrict__ Whb, const __nv_bfloat16* __restrict__ Wlb,
    __nv_bfloat16* __restrict__ Ohb, __nv_bfloat16* __restrict__ Olb,
    float* __restrict__ Of, const float* __restrict__ bias, float scale0)
{
    extern __shared__ __align__(16) __nv_bfloat16 sg[];

    const int z = blockIdx.z;
    const __nv_bfloat16* srcs[4] = {
        Ah, Al,
        Whb + (size_t)z * DM * DM, Wlb + (size_t)z * DM * DM
    };

    const int t = threadIdx.x, w = t >> 5, lane = t & 31;
    const int m0 = blockIdx.x * 128, n0 = blockIdx.y * 64;

    const unsigned sb = (unsigned)__cvta_generic_to_shared(sg);

    float acc[8][4];
    #pragma unroll
    for (int i = 0; i < 8; ++i)
        #pragma unroll
        for (int j = 0; j < 4; ++j) acc[i][j] = 0.0f;

    // stage copy: A hi/lo = 2*128 rows x 8 chunks (16B); W hi/lo = 2*64 x 8
    auto issue_stage = [&](int s) {
        const int k0 = s * 64;
        const unsigned dstb = sb + (s & 1) * GSTAGE_B;
        #pragma unroll
        for (int i = 0; i < 8; ++i) {          // A: 2048 chunks / 256 thr
            int idx = t + i * 256;
            int buf = idx >> 10;               // 0=hi 1=lo
            int rem = idx & 1023;
            int row = rem >> 3, ch = rem & 7;
            const __nv_bfloat16* src = srcs[buf] + (size_t)(m0 + row) * DM + k0 + ch * 8;
            cp_async16(dstb + (buf * GA_ELEM + row * GS + ch * 8) * 2, src);
        }
        #pragma unroll
        for (int i = 0; i < 4; ++i) {          // W: 1024 chunks
            int idx = t + i * 256;
            int buf = idx >> 9;
            int rem = idx & 511;
            int row = rem >> 3, ch = rem & 7;
            const __nv_bfloat16* src = srcs[2 + buf] + (size_t)(n0 + row) * DM + k0 + ch * 8;
            cp_async16(dstb + (2 * GA_ELEM + buf * GW_ELEM + row * GS + ch * 8) * 2, src);
        }
    };

    issue_stage(0);
    asm volatile("cp.async.commit_group;\n");

    for (int s = 0; s < 4; ++s) {
        if (s + 1 < 4) {
            issue_stage(s + 1);
            asm volatile("cp.async.commit_group;\n");
            asm volatile("cp.async.wait_group 1;\n");
        } else {
            asm volatile("cp.async.wait_group 0;\n");
        }
        __syncthreads();

        const unsigned st  = sb + (s & 1) * GSTAGE_B;
        const unsigned SAH = st;
        const unsigned SAL = st + GA_ELEM * 2;
        const unsigned SWH = st + 2 * GA_ELEM * 2;
        const unsigned SWL = SWH + GW_ELEM * 2;

        #pragma unroll
        for (int ks = 0; ks < 4; ++ks) {
            unsigned ah[4], al[4];
            int arow = 16 * w + (lane & 15);
            int acol = ks * 16 + ((lane & 16) ? 8 : 0);
            ldsm4(ah[0], ah[1], ah[2], ah[3], SAH + (arow * GS + acol) * 2);
            ldsm4(al[0], al[1], al[2], al[3], SAL + (arow * GS + acol) * 2);
            #pragma unroll
            for (int np = 0; np < 4; ++np) {
                int brow = np * 16 + (lane & 7) + ((lane & 16) ? 8 : 0);
                int bcol = ks * 16 + ((lane & 8) ? 8 : 0);
                unsigned bh0, bh1, bh2, bh3, bl0, bl1, bl2, bl3;
                ldsm4(bh0, bh1, bh2, bh3, SWH + (brow * GS + bcol) * 2);
                mma16816(acc[2 * np],     ah, bh0, bh1);
                mma16816(acc[2 * np + 1], ah, bh2, bh3);
                mma16816(acc[2 * np],     al, bh0, bh1);
                mma16816(acc[2 * np + 1], al, bh2, bh3);
                ldsm4(bl0, bl1, bl2, bl3, SWL + (brow * GS + bcol) * 2);
                mma16816(acc[2 * np],     ah, bl0, bl1);
                mma16816(acc[2 * np + 1], ah, bl2, bl3);
            }
        }
        __syncthreads();   // stage consumed before next issue overwrites it
    }

    const int r = lane >> 2, c2 = (lane & 3) * 2;
    const int row0 = m0 + 16 * w + r;
    if (Of) {
        #pragma unroll
        for (int j = 0; j < 8; ++j) {
            int col = n0 + 8 * j + c2;
            float b0v = bias[col], b1v = bias[col + 1];
            *(float2*)(Of + (size_t)row0 * DM + col) =
                make_float2(acc[j][0] + b0v, acc[j][1] + b1v);
            *(float2*)(Of + (size_t)(row0 + 8) * DM + col) =
                make_float2(acc[j][2] + b0v, acc[j][3] + b1v);
        }
    } else {
        const float sc = (z == 0) ? scale0 : 1.0f;
        __nv_bfloat16* Oh = Ohb + (size_t)z * BB * NN * DM;
        __nv_bfloat16* Ol = Olb + (size_t)z * BB * NN * DM;
        #pragma unroll
        for (int j = 0; j < 8; ++j) {
            int col = n0 + 8 * j + c2;
            unsigned h0, l0, h1, l1;
            split2(acc[j][0] * sc, acc[j][1] * sc, h0, l0);
            split2(acc[j][2] * sc, acc[j][3] * sc, h1, l1);
            *(unsigned*)(Oh + (size_t)row0 * DM + col)       = h0;
            *(unsigned*)(Ol + (size_t)row0 * DM + col)       = l0;
            *(unsigned*)(Oh + (size_t)(row0 + 8) * DM + col) = h1;
            *(unsigned*)(Ol + (size_t)(row0 + 8) * DM + col) = l1;
        }
    }
}

// ---------------------------------------------------------------------------
// Fused masked attention, bf16-split MMA, cp.async double-buffered K/V,
// bitmask adjacency. Grid (16, H, B), 256 threads = 8 warps.
// Restructured in 64-col halves to cut register pressure -> 2 CTAs/SM.
// ---------------------------------------------------------------------------
#define STAGE_B (4 * 128 * KS * 2)   // bytes per stage (Kh,Kl,Vh,Vl)
#define BUF_B   (128 * KS * 2)

__global__ __launch_bounds__(256, 2) void attn_mma(int dummy)
{
    extern __shared__ __align__(16) __nv_bfloat16 skv[];  // 2 stages

    const int t    = threadIdx.x;
    const int w    = t >> 5;
    const int lane = t & 31;
    const int r    = lane >> 2;
    const int c2   = (lane & 3) * 2;
    const int q0   = blockIdx.x * 128;
    const int h    = blockIdx.y;
    const int b    = blockIdx.z;

    const __nv_bfloat16* Qh = g_ph + ((size_t)b * NN + q0 + 16 * w) * DM + h * DHD;
    const __nv_bfloat16* Ql = g_pl + ((size_t)b * NN + q0 + 16 * w) * DM + h * DHD;
    const __nv_bfloat16* srcb[4] = {
        g_ph + ((size_t)(BB + b) * NN) * DM + h * DHD,        // K hi
        g_pl + ((size_t)(BB + b) * NN) * DM + h * DHD,        // K lo
        g_ph + ((size_t)(2 * BB + b) * NN) * DM + h * DHD,    // V hi
        g_pl + ((size_t)(2 * BB + b) * NN) * DM + h * DHD     // V lo
    };
    const unsigned* abr0 = g_adjb + ((size_t)b * NN + q0 + 16 * w + r) * (NN / 32);
    const unsigned* abr1 = abr0 + 8 * (NN / 32);

    const unsigned sb = (unsigned)__cvta_generic_to_shared(skv);

    // --- Q fragments (pre-scaled, pre-split) ---
    unsigned qh[2][4], ql[2][4];
    #pragma unroll
    for (int kc = 0; kc < 2; ++kc)
        #pragma unroll
        for (int i = 0; i < 4; ++i) {
            int ro = (i & 1) * 8;
            int co = (i >> 1) * 8;
            qh[kc][i] = *(const unsigned*)(Qh + (size_t)(r + ro) * DM + kc * 16 + co + c2);
            ql[kc][i] = *(const unsigned*)(Ql + (size_t)(r + ro) * DM + kc * 16 + co + c2);
        }

    float dacc[4][4];
    #pragma unroll
    for (int i = 0; i < 4; ++i)
        #pragma unroll
        for (int j = 0; j < 4; ++j) dacc[i][j] = 0.0f;
    float lsum0 = 0.0f, lsum1 = 0.0f;

    auto issue_tile = [&](int tt) {
        const int stage = tt & 1;
        const int m0 = tt * 128;
        const unsigned dstbase = sb + stage * STAGE_B;
        #pragma unroll
        for (int i = 0; i < 8; ++i) {
            int idx = t + i * 256;
            int buf = idx >> 9;
            int rem = idx & 511;
            int row = rem >> 2;
            int ch  = rem & 3;
            const __nv_bfloat16* src = srcb[buf] + (size_t)(m0 + row) * DM + ch * 8;
            cp_async16(dstbase + buf * BUF_B + row * (KS * 2) + ch * 16, src);
        }
    };

    issue_tile(0);
    asm volatile("cp.async.commit_group;\n");

    for (int tt = 0; tt < NN / 128; ++tt) {
        const int m0 = tt * 128;
        if (tt + 1 < NN / 128) {
            issue_tile(tt + 1);
            asm volatile("cp.async.commit_group;\n");
            asm volatile("cp.async.wait_group 1;\n");
        } else {
            asm volatile("cp.async.wait_group 0;\n");
        }
        __syncthreads();

        const unsigned st  = sb + (tt & 1) * STAGE_B;
        const unsigned KHI = st;
        const unsigned KLO = st + BUF_B;
        const unsigned VHI = st + 2 * BUF_B;
        const unsigned VLO = st + 3 * BUF_B;

        #pragma unroll
        for (int half = 0; half < 2; ++half) {
            // mask words for this 64-col half (2 words per row)
            uint2 m0v = *(const uint2*)(abr0 + (m0 >> 5) + 2 * half);
            uint2 m1v = *(const uint2*)(abr1 + (m0 >> 5) + 2 * half);
            unsigned mw0[2] = {m0v.x, m0v.y};
            unsigned mw1[2] = {m1v.x, m1v.y};

            unsigned pah[4][4], pal[4][4];

            #pragma unroll
            for (int nn = 0; nn < 4; ++nn) {
                const int np = half * 4 + nn;
                float s0[4] = {0.f, 0.f, 0.f, 0.f};
                float s1[4] = {0.f, 0.f, 0.f, 0.f};

                #pragma unroll
                for (int kc = 0; kc < 2; ++kc) {
                    int row = np * 16 + (lane & 7) + ((lane & 16) ? 8 : 0);
                    int col = kc * 16 + ((lane & 8) ? 8 : 0);
                    unsigned b0, b1, b2, b3;
                    ldsm4(b0, b1, b2, b3, KHI + (row * KS + col) * 2);
                    mma16816(s0, qh[kc], b0, b1);
                    mma16816(s1, qh[kc], b2, b3);
                    mma16816(s0, ql[kc], b0, b1);
                    mma16816(s1, ql[kc], b2, b3);
                    unsigned l0, l1, l2, l3;
                    ldsm4(l0, l1, l2, l3, KLO + (row * KS + col) * 2);
                    mma16816(s0, qh[kc], l0, l1);
                    mma16816(s1, qh[kc], l2, l3);
                }

                // mask + exp + pack (frees s0/s1 immediately)
                const unsigned w0 = mw0[nn >> 1], w1 = mw1[nn >> 1];
                const int bit0 = (np & 1) * 16 + c2;   // col np*16+c2 mod 32
                {
                    float p00 = ((w0 >> bit0) & 1)       ? __expf(s0[0]) : 0.0f;
                    float p01 = ((w0 >> (bit0 + 1)) & 1) ? __expf(s0[1]) : 0.0f;
                    float p10 = ((w1 >> bit0) & 1)       ? __expf(s0[2]) : 0.0f;
                    float p11 = ((w1 >> (bit0 + 1)) & 1) ? __expf(s0[3]) : 0.0f;
                    lsum0 += p00 + p01;
                    lsum1 += p10 + p11;
                    split2(p00, p01, pah[nn][0], pal[nn][0]);
                    split2(p10, p11, pah[nn][1], pal[nn][1]);
                }
                {
                    const int bit1 = bit0 + 8;
                    float p00 = ((w0 >> bit1) & 1)       ? __expf(s1[0]) : 0.0f;
                    float p01 = ((w0 >> (bit1 + 1)) & 1) ? __expf(s1[1]) : 0.0f;
                    float p10 = ((w1 >> bit1) & 1)       ? __expf(s1[2]) : 0.0f;
                    float p11 = ((w1 >> (bit1 + 1)) & 1) ? __expf(s1[3]) : 0.0f;
                    lsum0 += p00 + p01;
                    lsum1 += p10 + p11;
                    split2(p00, p01, pah[nn][2], pal[nn][2]);
                    split2(p10, p11, pah[nn][3], pal[nn][3]);
                }
            }

            // --- dacc += P(half) @ V(half rows) ---
            #pragma unroll
            for (int kt = 0; kt < 4; ++kt) {
                int row  = (half * 4 + kt) * 16 + (lane & 7) + ((lane & 8) ? 8 : 0);
                int colA = (lane & 16) ? 8 : 0;
                unsigned vh0, vh1, vh2, vh3, vl0, vl1, vl2, vl3;
                ldsm4t(vh0, vh1, vh2, vh3, VHI + (row * KS + colA) * 2);
                ldsm4t(vl0, vl1, vl2, vl3, VLO + (row * KS + colA) * 2);
                mma16816(dacc[0], pah[kt], vh0, vh1);
                mma16816(dacc[1], pah[kt], vh2, vh3);
                mma16816(dacc[0], pal[kt], vh0, vh1);
                mma16816(dacc[1], pal[kt], vh2, vh3);
                mma16816(dacc[0], pah[kt], vl0, vl1);
                mma16816(dacc[1], pah[kt], vl2, vl3);
                ldsm4t(vh0, vh1, vh2, vh3, VHI + (row * KS + colA + 16) * 2);
                ldsm4t(vl0, vl1, vl2, vl3, VLO + (row * KS + colA + 16) * 2);
                mma16816(dacc[2], pah[kt], vh0, vh1);
                mma16816(dacc[3], pah[kt], vh2, vh3);
                mma16816(dacc[2], pal[kt], vh0, vh1);
                mma16816(dacc[3], pal[kt], vh2, vh3);
                mma16816(dacc[2], pah[kt], vl0, vl1);
                mma16816(dacc[3], pah[kt], vl2, vl3);
            }
        }
        __syncthreads();   // all warps done reading this stage before reuse
    }

    // --- row-sum reduce (lanes xor 1,2 share a row) + split write ---
    lsum0 += __shfl_xor_sync(0xffffffffu, lsum0, 1);
    lsum0 += __shfl_xor_sync(0xffffffffu, lsum0, 2);
    lsum1 += __shfl_xor_sync(0xffffffffu, lsum1, 1);
    lsum1 += __shfl_xor_sync(0xffffffffu, lsum1, 2);
    float inv0 = 1.0f / lsum0;
    float inv1 = 1.0f / lsum1;

    __nv_bfloat16* ogh = g_ah + ((size_t)b * NN + q0 + 16 * w) * DM + h * DHD;
    __nv_bfloat16* ogl = g_al + ((size_t)b * NN + q0 + 16 * w) * DM + h * DHD;
    #pragma unroll
    for (int nd = 0; nd < 4; ++nd) {
        unsigned h0, l0, h1, l1;
        split2(dacc[nd][0] * inv0, dacc[nd][1] * inv0, h0, l0);
        split2(dacc[nd][2] * inv1, dacc[nd][3] * inv1, h1, l1);
        *(unsigned*)(ogh + (size_t)r * DM + nd * 8 + c2)       = h0;
        *(unsigned*)(ogl + (size_t)r * DM + nd * 8 + c2)       = l0;
        *(unsigned*)(ogh + (size_t)(r + 8) * DM + nd * 8 + c2) = h1;
        *(unsigned*)(ogl + (size_t)(r + 8) * DM + nd * 8 + c2) = l1;
    }
}

// ---------------------------------------------------------------------------
// Launch
// ---------------------------------------------------------------------------
extern "C" void kernel_launch(void* const* d_in, const int* in_sizes, int n_in,
                              void* d_out, int out_size)
{
    const float* x   = (const float*)d_in[0];
    const float* adj = (const float*)d_in[1];
    const float* Wq  = (const float*)d_in[2];
    const float* Wk  = (const float*)d_in[3];
    const float* Wv  = (const float*)d_in[4];
    const float* Wo  = (const float*)d_in[5];
    const float* bo  = (const float*)d_in[6];
    float* out = (float*)d_out;

    __nv_bfloat16 *xh, *xl, *wh, *wl, *ph, *pl, *ah, *al;
    cudaGetSymbolAddress((void**)&xh, g_xh);
    cudaGetSymbolAddress((void**)&xl, g_xl);
    cudaGetSymbolAddress((void**)&wh, g_wh);
    cudaGetSymbolAddress((void**)&wl, g_wl);
    cudaGetSymbolAddress((void**)&ph, g_ph);
    cudaGetSymbolAddress((void**)&pl, g_pl);
    cudaGetSymbolAddress((void**)&ah, g_ah);
    cudaGetSymbolAddress((void**)&al, g_al);

    const int gemm_smem = 2 * GSTAGE_B;   // 110592
    const int attn_smem = 2 * STAGE_B;    // 81920
    cudaFuncSetAttribute(gemm_split, cudaFuncAttributeMaxDynamicSharedMemorySize, gemm_smem);
    cudaFuncSetAttribute(attn_mma,   cudaFuncAttributeMaxDynamicSharedMemorySize, attn_smem);

    // prep
    split_x_kernel<<<1024, 256>>>(x);
    split_w_kernel<<<256, 256>>>(Wq, Wk, Wv, Wo);
    adj_bits_kernel<<<1024, 256>>>(adj);

    // QKV projections (z = 0,1,2), Q pre-scaled by 1/sqrt(dh)
    gemm_split<<<dim3(32, 4, 3), 256, gemm_smem>>>(
        xh, xl, wh, wl, ph, pl, nullptr, nullptr, 0.17677669529663687f);

    // attention
    attn_mma<<<dim3(NN / 128, HH, BB), 256, attn_smem>>>(0);

    // output projection: A @ Wo^T + bo
    gemm_split<<<dim3(32, 4, 1), 256, gemm_smem>>>(
        ah, al, wh + 3 * DM * DM, wl + 3 * DM * DM,
        nullptr, nullptr, out, bo, 1.0f);
}

// round 13
// speedup vs baseline: 3.4949x; 1.1624x over previous
#include <cuda_runtime.h>
#include <cuda_bf16.h>
#include <math.h>

// Problem constants
#define BB 2
#define NN 2048
#define DM 256     // d_model = H*DH
#define HH 8
#define DHD 32
#define KS 40      // attn smem row stride (bf16): 80B -> conflict-free ldmatrix
#define GS 72      // gemm smem row stride (bf16): 144B -> conflict-free ldmatrix

// ---------------------------------------------------------------------------
// Scratch (device globals: no allocations allowed)
// ---------------------------------------------------------------------------
__device__ __nv_bfloat16 g_xh[BB * NN * DM];          // x split hi
__device__ __nv_bfloat16 g_xl[BB * NN * DM];          // x split lo
__device__ __nv_bfloat16 g_wh[4 * DM * DM];           // Wq,Wk,Wv,Wo split hi
__device__ __nv_bfloat16 g_wl[4 * DM * DM];
__device__ __nv_bfloat16 g_ph[3 * BB * NN * DM];      // Q(scaled),K,V split hi
__device__ __nv_bfloat16 g_pl[3 * BB * NN * DM];
__device__ __nv_bfloat16 g_ah[BB * NN * DM];          // attn out split hi
__device__ __nv_bfloat16 g_al[BB * NN * DM];
__device__ unsigned      g_adjb[BB * NN * (NN / 32)]; // adjacency bitmask

// ---------------------------------------------------------------------------
// Helpers
// ---------------------------------------------------------------------------
__device__ __forceinline__ void mma16816(float d[4], const unsigned a[4],
                                         unsigned b0, unsigned b1)
{
    asm volatile(
        "mma.sync.aligned.m16n8k16.row.col.f32.bf16.bf16.f32 "
        "{%0,%1,%2,%3},{%4,%5,%6,%7},{%8,%9},{%0,%1,%2,%3};\n"
        : "+f"(d[0]), "+f"(d[1]), "+f"(d[2]), "+f"(d[3])
        : "r"(a[0]), "r"(a[1]), "r"(a[2]), "r"(a[3]), "r"(b0), "r"(b1));
}

__device__ __forceinline__ void ldsm4(unsigned &r0, unsigned &r1,
                                      unsigned &r2, unsigned &r3, unsigned addr)
{
    asm volatile("ldmatrix.sync.aligned.m8n8.x4.shared.b16 {%0,%1,%2,%3}, [%4];\n"
        : "=r"(r0), "=r"(r1), "=r"(r2), "=r"(r3) : "r"(addr));
}

__device__ __forceinline__ void ldsm4t(unsigned &r0, unsigned &r1,
                                       unsigned &r2, unsigned &r3, unsigned addr)
{
    asm volatile("ldmatrix.sync.aligned.m8n8.x4.trans.shared.b16 {%0,%1,%2,%3}, [%4];\n"
        : "=r"(r0), "=r"(r1), "=r"(r2), "=r"(r3) : "r"(addr));
}

// fast 2^x (same MUFU.EX2 approx class as __expf)
__device__ __forceinline__ float ex2(float x)
{
    float y;
    asm("ex2.approx.ftz.f32 %0, %1;" : "=f"(y) : "f"(x));
    return y;
}

// split two fp32 into (hi, lo) bf16x2 packed registers (x -> low half)
__device__ __forceinline__ void split2(float x, float y, unsigned &hi, unsigned &lo)
{
    __nv_bfloat16 hx = __float2bfloat16(x);
    __nv_bfloat16 hy = __float2bfloat16(y);
    float rx = x - __bfloat162float(hx);
    float ry = y - __bfloat162float(hy);
    __nv_bfloat162 hv = __halves2bfloat162(hx, hy);
    __nv_bfloat162 lv = __halves2bfloat162(__float2bfloat16(rx), __float2bfloat16(ry));
    hi = *reinterpret_cast<unsigned*>(&hv);
    lo = *reinterpret_cast<unsigned*>(&lv);
}

__device__ __forceinline__ void split_store4(float4 v, __nv_bfloat16* hp, __nv_bfloat16* lp)
{
    unsigned h01, l01, h23, l23;
    split2(v.x, v.y, h01, l01);
    split2(v.z, v.w, h23, l23);
    *reinterpret_cast<unsigned*>(hp)     = h01;
    *reinterpret_cast<unsigned*>(hp + 2) = h23;
    *reinterpret_cast<unsigned*>(lp)     = l01;
    *reinterpret_cast<unsigned*>(lp + 2) = l23;
}

__device__ __forceinline__ void cp_async16(unsigned dst, const void* src)
{
    asm volatile("cp.async.cg.shared.global [%0], [%1], 16;\n" :: "r"(dst), "l"(src));
}

// ---------------------------------------------------------------------------
// Fused prep kernel: blocks [0,1024) split x, [1024,1280) split W, rest adj bits
// ---------------------------------------------------------------------------
__global__ __launch_bounds__(256) void prep_kernel(
    const float* __restrict__ x,
    const float* __restrict__ wq, const float* __restrict__ wk,
    const float* __restrict__ wv, const float* __restrict__ wo,
    const float* __restrict__ adj)
{
    const int bid = blockIdx.x;
    if (bid < 1024) {
        int i = bid * 256 + threadIdx.x;               // 262144 float4
        float4 v = ((const float4*)x)[i];
        split_store4(v, g_xh + i * 4, g_xl + i * 4);
    } else if (bid < 1280) {
        int i = (bid - 1024) * 256 + threadIdx.x;      // 65536 float4
        int seg = i >> 14;
        int off = i & 16383;
        const float* src = (seg == 0) ? wq : (seg == 1) ? wk : (seg == 2) ? wv : wo;
        float4 v = ((const float4*)src)[off];
        split_store4(v, g_wh + (size_t)seg * DM * DM + off * 4,
                        g_wl + (size_t)seg * DM * DM + off * 4);
    } else {
        int gw   = ((bid - 1280) * 256 + threadIdx.x) >> 5;  // 8192 warps
        int lane = threadIdx.x & 31;
        size_t base = (size_t)gw * 1024;
        unsigned my = 0;
        #pragma unroll 8
        for (int k = 0; k < 32; ++k) {
            float v = adj[base + (size_t)k * 32 + lane];
            unsigned word = __ballot_sync(0xffffffffu, v != 0.0f);
            if (lane == k) my = word;
        }
        g_adjb[(size_t)gw * 32 + lane] = my;
    }
}

// ---------------------------------------------------------------------------
// bf16-split tensor-core GEMM: C[4096 x 256] = A @ W^T
// Block 128x64, 8 warps. K=256 in 4 stages of 64, cp.async depth-2 pipeline.
// MMAs emitted term-major across all 4 np blocks -> acc-chain distance 8.
// ---------------------------------------------------------------------------
#define GA_ELEM (128 * GS)
#define GW_ELEM (64 * GS)
#define GSTAGE_ELEM (2 * GA_ELEM + 2 * GW_ELEM)
#define GSTAGE_B (GSTAGE_ELEM * 2)

__global__ __launch_bounds__(256, 2) void gemm_split(
    const __nv_bfloat16* __restrict__ Ah, const __nv_bfloat16* __restrict__ Al,
    const __nv_bfloat16* __restrict__ Whb, const __nv_bfloat16* __restrict__ Wlb,
    __nv_bfloat16* __restrict__ Ohb, __nv_bfloat16* __restrict__ Olb,
    float* __restrict__ Of, const float* __restrict__ bias, float scale0)
{
    extern __shared__ __align__(16) __nv_bfloat16 sg[];

    const int z = blockIdx.z;
    const __nv_bfloat16* srcs[4] = {
        Ah, Al,
        Whb + (size_t)z * DM * DM, Wlb + (size_t)z * DM * DM
    };

    const int t = threadIdx.x, w = t >> 5, lane = t & 31;
    const int m0 = blockIdx.x * 128, n0 = blockIdx.y * 64;

    const unsigned sb = (unsigned)__cvta_generic_to_shared(sg);

    float acc[8][4];
    #pragma unroll
    for (int i = 0; i < 8; ++i)
        #pragma unroll
        for (int j = 0; j < 4; ++j) acc[i][j] = 0.0f;

    auto issue_stage = [&](int s) {
        const int k0 = s * 64;
        const unsigned dstb = sb + (s & 1) * GSTAGE_B;
        #pragma unroll
        for (int i = 0; i < 8; ++i) {          // A: 2048 chunks / 256 thr
            int idx = t + i * 256;
            int buf = idx >> 10;
            int rem = idx & 1023;
            int row = rem >> 3, ch = rem & 7;
            const __nv_bfloat16* src = srcs[buf] + (size_t)(m0 + row) * DM + k0 + ch * 8;
            cp_async16(dstb + (buf * GA_ELEM + row * GS + ch * 8) * 2, src);
        }
        #pragma unroll
        for (int i = 0; i < 4; ++i) {          // W: 1024 chunks
            int idx = t + i * 256;
            int buf = idx >> 9;
            int rem = idx & 511;
            int row = rem >> 3, ch = rem & 7;
            const __nv_bfloat16* src = srcs[2 + buf] + (size_t)(n0 + row) * DM + k0 + ch * 8;
            cp_async16(dstb + (2 * GA_ELEM + buf * GW_ELEM + row * GS + ch * 8) * 2, src);
        }
    };

    issue_stage(0);
    asm volatile("cp.async.commit_group;\n");

    for (int s = 0; s < 4; ++s) {
        if (s + 1 < 4) {
            issue_stage(s + 1);
            asm volatile("cp.async.commit_group;\n");
            asm volatile("cp.async.wait_group 1;\n");
        } else {
            asm volatile("cp.async.wait_group 0;\n");
        }
        __syncthreads();

        const unsigned st  = sb + (s & 1) * GSTAGE_B;
        const unsigned SAH = st;
        const unsigned SAL = st + GA_ELEM * 2;
        const unsigned SWH = st + 2 * GA_ELEM * 2;
        const unsigned SWL = SWH + GW_ELEM * 2;

        #pragma unroll
        for (int ks = 0; ks < 4; ++ks) {
            unsigned ah[4], al[4];
            int arow = 16 * w + (lane & 15);
            int acol = ks * 16 + ((lane & 16) ? 8 : 0);
            ldsm4(ah[0], ah[1], ah[2], ah[3], SAH + (arow * GS + acol) * 2);
            ldsm4(al[0], al[1], al[2], al[3], SAL + (arow * GS + acol) * 2);

            unsigned bh[4][4], bl[4][4];
            #pragma unroll
            for (int np = 0; np < 4; ++np) {
                int brow = np * 16 + (lane & 7) + ((lane & 16) ? 8 : 0);
                int bcol = ks * 16 + ((lane & 8) ? 8 : 0);
                ldsm4(bh[np][0], bh[np][1], bh[np][2], bh[np][3], SWH + (brow * GS + bcol) * 2);
                ldsm4(bl[np][0], bl[np][1], bl[np][2], bl[np][3], SWL + (brow * GS + bcol) * 2);
            }
            // term 1: ah * bh (per acc: first)
            #pragma unroll
            for (int np = 0; np < 4; ++np) {
                mma16816(acc[2 * np],     ah, bh[np][0], bh[np][1]);
                mma16816(acc[2 * np + 1], ah, bh[np][2], bh[np][3]);
            }
            // term 2: al * bh
            #pragma unroll
            for (int np = 0; np < 4; ++np) {
                mma16816(acc[2 * np],     al, bh[np][0], bh[np][1]);
                mma16816(acc[2 * np + 1], al, bh[np][2], bh[np][3]);
            }
            // term 3: ah * bl
            #pragma unroll
            for (int np = 0; np < 4; ++np) {
                mma16816(acc[2 * np],     ah, bl[np][0], bl[np][1]);
                mma16816(acc[2 * np + 1], ah, bl[np][2], bl[np][3]);
            }
        }
        __syncthreads();
    }

    const int r = lane >> 2, c2 = (lane & 3) * 2;
    const int row0 = m0 + 16 * w + r;
    if (Of) {
        #pragma unroll
        for (int j = 0; j < 8; ++j) {
            int col = n0 + 8 * j + c2;
            float b0v = bias[col], b1v = bias[col + 1];
            *(float2*)(Of + (size_t)row0 * DM + col) =
                make_float2(acc[j][0] + b0v, acc[j][1] + b1v);
            *(float2*)(Of + (size_t)(row0 + 8) * DM + col) =
                make_float2(acc[j][2] + b0v, acc[j][3] + b1v);
        }
    } else {
        const float sc = (z == 0) ? scale0 : 1.0f;
        __nv_bfloat16* Oh = Ohb + (size_t)z * BB * NN * DM;
        __nv_bfloat16* Ol = Olb + (size_t)z * BB * NN * DM;
        #pragma unroll
        for (int j = 0; j < 8; ++j) {
            int col = n0 + 8 * j + c2;
            unsigned h0, l0, h1, l1;
            split2(acc[j][0] * sc, acc[j][1] * sc, h0, l0);
            split2(acc[j][2] * sc, acc[j][3] * sc, h1, l1);
            *(unsigned*)(Oh + (size_t)row0 * DM + col)       = h0;
            *(unsigned*)(Ol + (size_t)row0 * DM + col)       = l0;
            *(unsigned*)(Oh + (size_t)(row0 + 8) * DM + col) = h1;
            *(unsigned*)(Ol + (size_t)(row0 + 8) * DM + col) = l1;
        }
    }
}

// ---------------------------------------------------------------------------
// Fused masked attention, bf16-split MMA, cp.async double-buffered K/V,
// bitmask adjacency. Q is pre-scaled by (1/sqrt(dh))*log2(e): p = 2^s.
// MMAs reordered term-major across independent accumulators (distance 4).
// ---------------------------------------------------------------------------
#define STAGE_B (4 * 128 * KS * 2)   // bytes per stage (Kh,Kl,Vh,Vl)
#define BUF_B   (128 * KS * 2)

__global__ __launch_bounds__(256, 2) void attn_mma(int dummy)
{
    extern __shared__ __align__(16) __nv_bfloat16 skv[];  // 2 stages

    const int t    = threadIdx.x;
    const int w    = t >> 5;
    const int lane = t & 31;
    const int r    = lane >> 2;
    const int c2   = (lane & 3) * 2;
    const int q0   = blockIdx.x * 128;
    const int h    = blockIdx.y;
    const int b    = blockIdx.z;

    const __nv_bfloat16* Qh = g_ph + ((size_t)b * NN + q0 + 16 * w) * DM + h * DHD;
    const __nv_bfloat16* Ql = g_pl + ((size_t)b * NN + q0 + 16 * w) * DM + h * DHD;
    const __nv_bfloat16* srcb[4] = {
        g_ph + ((size_t)(BB + b) * NN) * DM + h * DHD,        // K hi
        g_pl + ((size_t)(BB + b) * NN) * DM + h * DHD,        // K lo
        g_ph + ((size_t)(2 * BB + b) * NN) * DM + h * DHD,    // V hi
        g_pl + ((size_t)(2 * BB + b) * NN) * DM + h * DHD     // V lo
    };
    const unsigned* abr0 = g_adjb + ((size_t)b * NN + q0 + 16 * w + r) * (NN / 32);
    const unsigned* abr1 = abr0 + 8 * (NN / 32);

    const unsigned sb = (unsigned)__cvta_generic_to_shared(skv);

    // --- Q fragments (pre-scaled, pre-split) ---
    unsigned qh[2][4], ql[2][4];
    #pragma unroll
    for (int kc = 0; kc < 2; ++kc)
        #pragma unroll
        for (int i = 0; i < 4; ++i) {
            int ro = (i & 1) * 8;
            int co = (i >> 1) * 8;
            qh[kc][i] = *(const unsigned*)(Qh + (size_t)(r + ro) * DM + kc * 16 + co + c2);
            ql[kc][i] = *(const unsigned*)(Ql + (size_t)(r + ro) * DM + kc * 16 + co + c2);
        }

    float dacc[4][4];
    #pragma unroll
    for (int i = 0; i < 4; ++i)
        #pragma unroll
        for (int j = 0; j < 4; ++j) dacc[i][j] = 0.0f;
    float lsum0 = 0.0f, lsum1 = 0.0f;

    auto issue_tile = [&](int tt) {
        const int stage = tt & 1;
        const int m0 = tt * 128;
        const unsigned dstbase = sb + stage * STAGE_B;
        #pragma unroll
        for (int i = 0; i < 8; ++i) {
            int idx = t + i * 256;
            int buf = idx >> 9;
            int rem = idx & 511;
            int row = rem >> 2;
            int ch  = rem & 3;
            const __nv_bfloat16* src = srcb[buf] + (size_t)(m0 + row) * DM + ch * 8;
            cp_async16(dstbase + buf * BUF_B + row * (KS * 2) + ch * 16, src);
        }
    };

    issue_tile(0);
    asm volatile("cp.async.commit_group;\n");

    for (int tt = 0; tt < NN / 128; ++tt) {
        const int m0 = tt * 128;
        if (tt + 1 < NN / 128) {
            issue_tile(tt + 1);
            asm volatile("cp.async.commit_group;\n");
            asm volatile("cp.async.wait_group 1;\n");
        } else {
            asm volatile("cp.async.wait_group 0;\n");
        }
        __syncthreads();

        const unsigned st  = sb + (tt & 1) * STAGE_B;
        const unsigned KHI = st;
        const unsigned KLO = st + BUF_B;
        const unsigned VHI = st + 2 * BUF_B;
        const unsigned VLO = st + 3 * BUF_B;

        #pragma unroll
        for (int half = 0; half < 2; ++half) {
            uint2 m0v = *(const uint2*)(abr0 + (m0 >> 5) + 2 * half);
            uint2 m1v = *(const uint2*)(abr1 + (m0 >> 5) + 2 * half);
            unsigned mw0[2] = {m0v.x, m0v.y};
            unsigned mw1[2] = {m1v.x, m1v.y};

            unsigned pah[4][4], pal[4][4];

            // process np in pairs: 4 independent s accumulators, distance-4 chains
            #pragma unroll
            for (int nnp = 0; nnp < 2; ++nnp) {
                const int npA = half * 4 + 2 * nnp;
                const int npB = npA + 1;
                float sA0[4] = {0.f, 0.f, 0.f, 0.f};
                float sA1[4] = {0.f, 0.f, 0.f, 0.f};
                float sB0[4] = {0.f, 0.f, 0.f, 0.f};
                float sB1[4] = {0.f, 0.f, 0.f, 0.f};

                #pragma unroll
                for (int kc = 0; kc < 2; ++kc) {
                    const int rbase = (lane & 7) + ((lane & 16) ? 8 : 0);
                    const int col   = kc * 16 + ((lane & 8) ? 8 : 0);
                    unsigned kAh[4], kAl[4], kBh[4], kBl[4];
                    ldsm4(kAh[0], kAh[1], kAh[2], kAh[3], KHI + ((npA * 16 + rbase) * KS + col) * 2);
                    ldsm4(kAl[0], kAl[1], kAl[2], kAl[3], KLO + ((npA * 16 + rbase) * KS + col) * 2);
                    ldsm4(kBh[0], kBh[1], kBh[2], kBh[3], KHI + ((npB * 16 + rbase) * KS + col) * 2);
                    ldsm4(kBl[0], kBl[1], kBl[2], kBl[3], KLO + ((npB * 16 + rbase) * KS + col) * 2);
                    // term hh
                    mma16816(sA0, qh[kc], kAh[0], kAh[1]);
                    mma16816(sA1, qh[kc], kAh[2], kAh[3]);
                    mma16816(sB0, qh[kc], kBh[0], kBh[1]);
                    mma16816(sB1, qh[kc], kBh[2], kBh[3]);
                    // term lh (ql x kh)
                    mma16816(sA0, ql[kc], kAh[0], kAh[1]);
                    mma16816(sA1, ql[kc], kAh[2], kAh[3]);
                    mma16816(sB0, ql[kc], kBh[0], kBh[1]);
                    mma16816(sB1, ql[kc], kBh[2], kBh[3]);
                    // term hl (qh x kl)
                    mma16816(sA0, qh[kc], kAl[0], kAl[1]);
                    mma16816(sA1, qh[kc], kAl[2], kAl[3]);
                    mma16816(sB0, qh[kc], kBl[0], kBl[1]);
                    mma16816(sB1, qh[kc], kBl[2], kBl[3]);
                }

                // mask + 2^s + pack for npA then npB
                #pragma unroll
                for (int e = 0; e < 2; ++e) {
                    const int nn = 2 * nnp + e;
                    const int np = half * 4 + nn;
                    float* s0 = e ? sB0 : sA0;
                    float* s1 = e ? sB1 : sA1;
                    const unsigned w0 = mw0[nn >> 1], w1 = mw1[nn >> 1];
                    const int bit0 = (np & 1) * 16 + c2;
                    {
                        float p00 = ((w0 >> bit0) & 1)       ? ex2(s0[0]) : 0.0f;
                        float p01 = ((w0 >> (bit0 + 1)) & 1) ? ex2(s0[1]) : 0.0f;
                        float p10 = ((w1 >> bit0) & 1)       ? ex2(s0[2]) : 0.0f;
                        float p11 = ((w1 >> (bit0 + 1)) & 1) ? ex2(s0[3]) : 0.0f;
                        lsum0 += p00 + p01;
                        lsum1 += p10 + p11;
                        split2(p00, p01, pah[nn][0], pal[nn][0]);
                        split2(p10, p11, pah[nn][1], pal[nn][1]);
                    }
                    {
                        const int bit1 = bit0 + 8;
                        float p00 = ((w0 >> bit1) & 1)       ? ex2(s1[0]) : 0.0f;
                        float p01 = ((w0 >> (bit1 + 1)) & 1) ? ex2(s1[1]) : 0.0f;
                        float p10 = ((w1 >> bit1) & 1)       ? ex2(s1[2]) : 0.0f;
                        float p11 = ((w1 >> (bit1 + 1)) & 1) ? ex2(s1[3]) : 0.0f;
                        lsum0 += p00 + p01;
                        lsum1 += p10 + p11;
                        split2(p00, p01, pah[nn][2], pal[nn][2]);
                        split2(p10, p11, pah[nn][3], pal[nn][3]);
                    }
                }
            }

            // --- dacc += P(half) @ V(half rows): preload 16 V regs, distance-4 ---
            #pragma unroll
            for (int kt = 0; kt < 4; ++kt) {
                const int row  = (half * 4 + kt) * 16 + (lane & 7) + ((lane & 8) ? 8 : 0);
                const int colA = (lane & 16) ? 8 : 0;
                unsigned avh[4], avl[4], bvh[4], bvl[4];
                ldsm4t(avh[0], avh[1], avh[2], avh[3], VHI + (row * KS + colA) * 2);
                ldsm4t(avl[0], avl[1], avl[2], avl[3], VLO + (row * KS + colA) * 2);
                ldsm4t(bvh[0], bvh[1], bvh[2], bvh[3], VHI + (row * KS + colA + 16) * 2);
                ldsm4t(bvl[0], bvl[1], bvl[2], bvl[3], VLO + (row * KS + colA + 16) * 2);
                // term ph * vh
                mma16816(dacc[0], pah[kt], avh[0], avh[1]);
                mma16816(dacc[1], pah[kt], avh[2], avh[3]);
                mma16816(dacc[2], pah[kt], bvh[0], bvh[1]);
                mma16816(dacc[3], pah[kt], bvh[2], bvh[3]);
                // term pl * vh
                mma16816(dacc[0], pal[kt], avh[0], avh[1]);
                mma16816(dacc[1], pal[kt], avh[2], avh[3]);
                mma16816(dacc[2], pal[kt], bvh[0], bvh[1]);
                mma16816(dacc[3], pal[kt], bvh[2], bvh[3]);
                // term ph * vl
                mma16816(dacc[0], pah[kt], avl[0], avl[1]);
                mma16816(dacc[1], pah[kt], avl[2], avl[3]);
                mma16816(dacc[2], pah[kt], bvl[0], bvl[1]);
                mma16816(dacc[3], pah[kt], bvl[2], bvl[3]);
            }
        }
        __syncthreads();
    }

    // --- row-sum reduce (lanes xor 1,2 share a row) + split write ---
    lsum0 += __shfl_xor_sync(0xffffffffu, lsum0, 1);
    lsum0 += __shfl_xor_sync(0xffffffffu, lsum0, 2);
    lsum1 += __shfl_xor_sync(0xffffffffu, lsum1, 1);
    lsum1 += __shfl_xor_sync(0xffffffffu, lsum1, 2);
    float inv0 = 1.0f / lsum0;
    float inv1 = 1.0f / lsum1;

    __nv_bfloat16* ogh = g_ah + ((size_t)b * NN + q0 + 16 * w) * DM + h * DHD;
    __nv_bfloat16* ogl = g_al + ((size_t)b * NN + q0 + 16 * w) * DM + h * DHD;
    #pragma unroll
    for (int nd = 0; nd < 4; ++nd) {
        unsigned h0, l0, h1, l1;
        split2(dacc[nd][0] * inv0, dacc[nd][1] * inv0, h0, l0);
        split2(dacc[nd][2] * inv1, dacc[nd][3] * inv1, h1, l1);
        *(unsigned*)(ogh + (size_t)r * DM + nd * 8 + c2)       = h0;
        *(unsigned*)(ogl + (size_t)r * DM + nd * 8 + c2)       = l0;
        *(unsigned*)(ogh + (size_t)(r + 8) * DM + nd * 8 + c2) = h1;
        *(unsigned*)(ogl + (size_t)(r + 8) * DM + nd * 8 + c2) = l1;
    }
}

// ---------------------------------------------------------------------------
// Launch
// ---------------------------------------------------------------------------
extern "C" void kernel_launch(void* const* d_in, const int* in_sizes, int n_in,
                              void* d_out, int out_size)
{
    const float* x   = (const float*)d_in[0];
    const float* adj = (const float*)d_in[1];
    const float* Wq  = (const float*)d_in[2];
    const float* Wk  = (const float*)d_in[3];
    const float* Wv  = (const float*)d_in[4];
    const float* Wo  = (const float*)d_in[5];
    const float* bo  = (const float*)d_in[6];
    float* out = (float*)d_out;

    __nv_bfloat16 *xh, *xl, *wh, *wl, *ph, *pl, *ah, *al;
    cudaGetSymbolAddress((void**)&xh, g_xh);
    cudaGetSymbolAddress((void**)&xl, g_xl);
    cudaGetSymbolAddress((void**)&wh, g_wh);
    cudaGetSymbolAddress((void**)&wl, g_wl);
    cudaGetSymbolAddress((void**)&ph, g_ph);
    cudaGetSymbolAddress((void**)&pl, g_pl);
    cudaGetSymbolAddress((void**)&ah, g_ah);
    cudaGetSymbolAddress((void**)&al, g_al);

    const int gemm_smem = 2 * GSTAGE_B;   // 110592
    const int attn_smem = 2 * STAGE_B;    // 81920
    cudaFuncSetAttribute(gemm_split, cudaFuncAttributeMaxDynamicSharedMemorySize, gemm_smem);
    cudaFuncSetAttribute(attn_mma,   cudaFuncAttributeMaxDynamicSharedMemorySize, attn_smem);

    // fused prep: 1024 (x) + 256 (W) + 1024 (adj) blocks
    prep_kernel<<<2304, 256>>>(x, Wq, Wk, Wv, Wo, adj);

    // QKV projections; Q pre-scaled by (1/sqrt(dh)) * log2(e) so attn uses 2^s
    gemm_split<<<dim3(32, 4, 3), 256, gemm_smem>>>(
        xh, xl, wh, wl, ph, pl, nullptr, nullptr,
        0.17677669529663687f * 1.4426950408889634f);

    // attention
    attn_mma<<<dim3(NN / 128, HH, BB), 256, attn_smem>>>(0);

    // output projection: A @ Wo^T + bo
    gemm_split<<<dim3(32, 4, 1), 256, gemm_smem>>>(
        ah, al, wh + 3 * DM * DM, wl + 3 * DM * DM,
        nullptr, nullptr, out, bo, 1.0f);
}